// round 2
// baseline (speedup 1.0000x reference)
#include <cuda_runtime.h>
#include <math.h>

// Problem constants (fixed by reference setup_inputs)
#define BATCH 2
#define TT    8
#define HH    28
#define WW    28
#define CC    768
#define NHEAD 12
#define HD    64
#define NTOK  785        // 1 + 28*28
#define HP    14
#define NQ    197        // 1 + 14*14
#define BT    (BATCH*TT) // 16
#define MROWS (BT*NQ)    // 3152
#define LSEQ  (TT*NQ)    // 1576
#define EPSLN 1e-5f

// Scratch (static device globals; no runtime allocation allowed)
__device__ float g_poolq[MROWS*CC];
__device__ float g_poolk[MROWS*CC];
__device__ float g_poolv[MROWS*CC];
__device__ float g_q[MROWS*CC];   // (b, h, l, d) layout
__device__ float g_k[MROWS*CC];
__device__ float g_v[MROWS*CC];
__device__ float g_ao[MROWS*CC];  // (b*L, C) layout

// ---------------------------------------------------------------------------
// Kernel 1: depthwise 3x3 stride-2 pool on body tokens + per-(token,head)
// layernorm over hd=64 channels. One warp handles one (bt, token, head):
// lane owns channels {lane, lane+32}.
// src: (BT, 785, 768) row-major. dst: (BT, 197, 768) row-major.
// ---------------------------------------------------------------------------
__global__ void pool_norm_kernel(const float* __restrict__ src,
                                 const float* __restrict__ cw,   // (3,3,1,64)
                                 const float* __restrict__ gam,  // (64)
                                 const float* __restrict__ bet,  // (64)
                                 float* __restrict__ dst) {
    int n    = blockIdx.x;   // 0..196 output token
    int bt   = blockIdx.y;   // 0..15
    int h    = blockIdx.z;   // 0..11
    int lane = threadIdx.x;  // 0..31
    int c0 = lane, c1 = lane + 32;

    float v0, v1;
    if (n == 0) {
        const float* p = src + ((size_t)bt * NTOK) * CC + h * HD;
        v0 = p[c0]; v1 = p[c1];
    } else {
        int io = (n - 1) / HP, jo = (n - 1) % HP;
        v0 = 0.f; v1 = 0.f;
        #pragma unroll
        for (int di = 0; di < 3; ++di) {
            int ii = 2 * io - 1 + di;
            if (ii < 0 || ii >= HH) continue;
            #pragma unroll
            for (int dj = 0; dj < 3; ++dj) {
                int jj = 2 * jo - 1 + dj;
                if (jj < 0 || jj >= WW) continue;
                const float* p = src + ((size_t)bt * NTOK + 1 + ii * WW + jj) * CC + h * HD;
                v0 += p[c0] * cw[(di * 3 + dj) * HD + c0];
                v1 += p[c1] * cw[(di * 3 + dj) * HD + c1];
            }
        }
    }
    // layernorm over 64 channels (2 per lane, warp reduce)
    float s = v0 + v1;
    #pragma unroll
    for (int off = 16; off > 0; off >>= 1) s += __shfl_xor_sync(0xffffffffu, s, off);
    float mu = s * (1.f / 64.f);
    float d0 = v0 - mu, d1 = v1 - mu;
    float vs = d0 * d0 + d1 * d1;
    #pragma unroll
    for (int off = 16; off > 0; off >>= 1) vs += __shfl_xor_sync(0xffffffffu, vs, off);
    float inv = rsqrtf(vs * (1.f / 64.f) + EPSLN);

    float* o = dst + ((size_t)bt * NQ + n) * CC + h * HD;
    o[c0] = d0 * inv * gam[c0] + bet[c0];
    o[c1] = d1 * inv * gam[c1] + bet[c1];
}

// ---------------------------------------------------------------------------
// Kernel 2: SGEMM  C[M,N] = A[M,K] @ W[N,K]^T  (classic 128x128x8, 8x8/thread)
// MODE 0: scatter output to attention layout (b, head, l, d)
// MODE 1: plain row-major + bias
// ---------------------------------------------------------------------------
#define GBM 128
#define GBN 128
#define GBK 8

template<int MODE>
__global__ __launch_bounds__(256)
void sgemm_kernel(const float* __restrict__ A, const float* __restrict__ W,
                  const float* __restrict__ bias, float* __restrict__ C,
                  int M, int N, int K) {
    __shared__ float As[GBK][GBM];
    __shared__ float Bs[GBK][GBN];
    int tid  = threadIdx.x;
    int row0 = blockIdx.y * GBM;
    int col0 = blockIdx.x * GBN;
    int tx = tid % 16, ty = tid / 16;

    int arow = tid >> 1;            // 0..127
    int acol = (tid & 1) * 4;       // 0 or 4
    int brow = tid >> 1;
    int bcol = (tid & 1) * 4;

    float acc[8][8];
    #pragma unroll
    for (int i = 0; i < 8; i++)
        #pragma unroll
        for (int j = 0; j < 8; j++) acc[i][j] = 0.f;

    for (int k0 = 0; k0 < K; k0 += GBK) {
        float4 av = make_float4(0.f, 0.f, 0.f, 0.f);
        if (row0 + arow < M)
            av = *(const float4*)(A + (size_t)(row0 + arow) * K + k0 + acol);
        As[acol + 0][arow] = av.x; As[acol + 1][arow] = av.y;
        As[acol + 2][arow] = av.z; As[acol + 3][arow] = av.w;

        float4 bv = *(const float4*)(W + (size_t)(col0 + brow) * K + k0 + bcol);
        Bs[bcol + 0][brow] = bv.x; Bs[bcol + 1][brow] = bv.y;
        Bs[bcol + 2][brow] = bv.z; Bs[bcol + 3][brow] = bv.w;
        __syncthreads();

        #pragma unroll
        for (int k = 0; k < GBK; k++) {
            float4 a0 = *(const float4*)&As[k][ty * 8];
            float4 a1 = *(const float4*)&As[k][ty * 8 + 4];
            float4 b0 = *(const float4*)&Bs[k][tx * 8];
            float4 b1 = *(const float4*)&Bs[k][tx * 8 + 4];
            float am[8] = {a0.x, a0.y, a0.z, a0.w, a1.x, a1.y, a1.z, a1.w};
            float bn[8] = {b0.x, b0.y, b0.z, b0.w, b1.x, b1.y, b1.z, b1.w};
            #pragma unroll
            for (int i = 0; i < 8; i++)
                #pragma unroll
                for (int j = 0; j < 8; j++)
                    acc[i][j] += am[i] * bn[j];
        }
        __syncthreads();
    }

    #pragma unroll
    for (int i = 0; i < 8; i++) {
        int m = row0 + ty * 8 + i;
        if (m >= M) continue;
        if (MODE == 0) {
            int b = m / LSEQ, l = m % LSEQ;
            #pragma unroll
            for (int j = 0; j < 8; j++) {
                int o = col0 + tx * 8 + j;
                C[(((size_t)(b * NHEAD + (o >> 6)) * LSEQ + l) << 6) + (o & 63)] = acc[i][j];
            }
        } else {
            #pragma unroll
            for (int j = 0; j < 8; j++) {
                int o = col0 + tx * 8 + j;
                C[(size_t)m * N + o] = acc[i][j] + bias[o];
            }
        }
    }
}

// ---------------------------------------------------------------------------
// Kernel 3: flash attention fp32. One thread per query row (64-row Q tiles),
// K/V staged in smem, online softmax, fused Q-residual (skipped for l==0).
// Q/K/V in (b,h,l,d) layout; output to (b*l, C) layout.
// ---------------------------------------------------------------------------
#define QTI 64
#define KTI 64

__global__ __launch_bounds__(64)
void flash_kernel(const float* __restrict__ Q, const float* __restrict__ Kp,
                  const float* __restrict__ Vp, float* __restrict__ O) {
    __shared__ float Ks[KTI * HD];
    __shared__ float Vs[KTI * HD];
    int bh  = blockIdx.y;
    int b   = bh / NHEAD;
    int h   = bh % NHEAD;
    int tid = threadIdx.x;
    int l   = blockIdx.x * QTI + tid;
    bool valid = l < LSEQ;

    const float4* qp = (const float4*)(Q + ((size_t)bh * LSEQ + (valid ? l : 0)) * HD);
    float4 qr[16];
    #pragma unroll
    for (int i = 0; i < 16; i++) qr[i] = qp[i];

    float4 oa[16];
    #pragma unroll
    for (int i = 0; i < 16; i++) oa[i] = make_float4(0.f, 0.f, 0.f, 0.f);
    float mprev = -1e30f, ssum = 0.f;

    for (int kt0 = 0; kt0 < LSEQ; kt0 += KTI) {
        int jmax = min(KTI, LSEQ - kt0);
        __syncthreads();
        if (tid < jmax) {
            const float4* kr = (const float4*)(Kp + ((size_t)bh * LSEQ + kt0 + tid) * HD);
            const float4* vr = (const float4*)(Vp + ((size_t)bh * LSEQ + kt0 + tid) * HD);
            float4* kd = (float4*)(Ks + tid * HD);
            float4* vd = (float4*)(Vs + tid * HD);
            #pragma unroll
            for (int i = 0; i < 16; i++) { kd[i] = kr[i]; vd[i] = vr[i]; }
        }
        __syncthreads();
        if (!valid) continue;

        for (int jc = 0; jc < jmax; jc += 16) {
            int cmax = min(16, jmax - jc);
            float sj[16];
            float mnew = mprev;
            for (int j = 0; j < cmax; j++) {
                const float4* kr4 = (const float4*)(Ks + (jc + j) * HD);
                float4 a4 = make_float4(0.f, 0.f, 0.f, 0.f);
                #pragma unroll
                for (int i = 0; i < 16; i++) {
                    float4 kv = kr4[i];
                    a4.x += qr[i].x * kv.x; a4.y += qr[i].y * kv.y;
                    a4.z += qr[i].z * kv.z; a4.w += qr[i].w * kv.w;
                }
                float s = 0.125f * (a4.x + a4.y + a4.z + a4.w);  // hd^-0.5 = 1/8
                sj[j] = s;
                mnew = fmaxf(mnew, s);
            }
            float corr = __expf(mprev - mnew);
            ssum *= corr;
            #pragma unroll
            for (int i = 0; i < 16; i++) {
                oa[i].x *= corr; oa[i].y *= corr; oa[i].z *= corr; oa[i].w *= corr;
            }
            for (int j = 0; j < cmax; j++) {
                float p = __expf(sj[j] - mnew);
                ssum += p;
                const float4* vr4 = (const float4*)(Vs + (jc + j) * HD);
                #pragma unroll
                for (int i = 0; i < 16; i++) {
                    float4 vv = vr4[i];
                    oa[i].x += p * vv.x; oa[i].y += p * vv.y;
                    oa[i].z += p * vv.z; oa[i].w += p * vv.w;
                }
            }
            mprev = mnew;
        }
    }

    if (valid) {
        float inv = 1.f / ssum;
        float* op = O + ((size_t)(b * LSEQ + l)) * CC + h * HD;
        float resid = (l != 0) ? 1.f : 0.f;   // out[:, :, 1:, :] += q[:, :, 1:, :]
        #pragma unroll
        for (int i = 0; i < 16; i++) {
            float4 r;
            r.x = oa[i].x * inv + resid * qr[i].x;
            r.y = oa[i].y * inv + resid * qr[i].y;
            r.z = oa[i].z * inv + resid * qr[i].z;
            r.w = oa[i].w * inv + resid * qr[i].w;
            ((float4*)op)[i] = r;
        }
    }
}

// ---------------------------------------------------------------------------
extern "C" void kernel_launch(void* const* d_in, const int* in_sizes, int n_in,
                              void* d_out, int out_size) {
    const float* x  = (const float*)d_in[0];
    const float* xr = (const float*)d_in[1];
    const float* wq = (const float*)d_in[2];
    const float* wk = (const float*)d_in[3];
    const float* wv = (const float*)d_in[4];
    const float* wp = (const float*)d_in[5];
    const float* bp = (const float*)d_in[6];
    const float* cq = (const float*)d_in[7];
    const float* ck = (const float*)d_in[8];
    const float* cv = (const float*)d_in[9];
    const float* gq = (const float*)d_in[10];
    const float* bq = (const float*)d_in[11];
    const float* gk = (const float*)d_in[12];
    const float* bk = (const float*)d_in[13];
    const float* gv = (const float*)d_in[14];
    const float* bv = (const float*)d_in[15];
    float* out = (float*)d_out;

    float *pq, *pk, *pv, *qd, *kd, *vd, *ao;
    cudaGetSymbolAddress((void**)&pq, g_poolq);
    cudaGetSymbolAddress((void**)&pk, g_poolk);
    cudaGetSymbolAddress((void**)&pv, g_poolv);
    cudaGetSymbolAddress((void**)&qd, g_q);
    cudaGetSymbolAddress((void**)&kd, g_k);
    cudaGetSymbolAddress((void**)&vd, g_v);
    cudaGetSymbolAddress((void**)&ao, g_ao);

    dim3 pg(NQ, BT, NHEAD);
    pool_norm_kernel<<<pg, 32>>>(x,  cq, gq, bq, pq);
    pool_norm_kernel<<<pg, 32>>>(xr, ck, gk, bk, pk);
    pool_norm_kernel<<<pg, 32>>>(xr, cv, gv, bv, pv);

    dim3 gg(CC / GBN, (MROWS + GBM - 1) / GBM);
    sgemm_kernel<0><<<gg, 256>>>(pq, wq, nullptr, qd, MROWS, CC, CC);
    sgemm_kernel<0><<<gg, 256>>>(pk, wk, nullptr, kd, MROWS, CC, CC);
    sgemm_kernel<0><<<gg, 256>>>(pv, wv, nullptr, vd, MROWS, CC, CC);

    dim3 fg((LSEQ + QTI - 1) / QTI, BATCH * NHEAD);
    flash_kernel<<<fg, 64>>>(qd, kd, vd, ao);

    sgemm_kernel<1><<<gg, 256>>>(ao, wp, bp, out, MROWS, CC, CC);
}

// round 3
// speedup vs baseline: 3.5134x; 3.5134x over previous
#include <cuda_runtime.h>
#include <math.h>
#include <stdint.h>

// Problem constants (fixed by reference setup_inputs)
#define BATCH 2
#define TT    8
#define HH    28
#define WW    28
#define CC    768
#define NHEAD 12
#define HD    64
#define NTOK  785        // 1 + 28*28
#define HP    14
#define NQ    197        // 1 + 14*14
#define BT    (BATCH*TT) // 16
#define MROWS (BT*NQ)    // 3152
#define LSEQ  (TT*NQ)    // 1576
#define EPSLN 1e-5f

// Scratch (static device globals; no runtime allocation allowed)
__device__ float g_poolq[MROWS*CC];
__device__ float g_poolk[MROWS*CC];
__device__ float g_poolv[MROWS*CC];
__device__ float g_q[MROWS*CC];   // (b, h, l, d) layout
__device__ float g_k[MROWS*CC];
__device__ float g_v[MROWS*CC];
__device__ float g_ao[MROWS*CC];  // (b*L, C) layout

// ---------------------------------------------------------------------------
// helpers: tf32 convert + mma
// ---------------------------------------------------------------------------
__device__ __forceinline__ uint32_t f2tf(float x) {
    uint32_t r;
    asm("cvt.rna.tf32.f32 %0, %1;" : "=r"(r) : "f"(x));
    return r;
}
__device__ __forceinline__ float f2tff(float x) {
    return __uint_as_float(f2tf(x));
}
__device__ __forceinline__ void mma_tf32(float* d, const uint32_t* a, const uint32_t* b) {
    asm volatile(
        "mma.sync.aligned.m16n8k8.row.col.f32.tf32.tf32.f32 "
        "{%0,%1,%2,%3}, {%4,%5,%6,%7}, {%8,%9}, {%0,%1,%2,%3};\n"
        : "+f"(d[0]), "+f"(d[1]), "+f"(d[2]), "+f"(d[3])
        : "r"(a[0]), "r"(a[1]), "r"(a[2]), "r"(a[3]), "r"(b[0]), "r"(b[1]));
}

// ---------------------------------------------------------------------------
// Kernel 1: depthwise 3x3 stride-2 pool on body tokens + per-(token,head)
// layernorm over hd=64 channels. One warp per (bt, token, head).
// ---------------------------------------------------------------------------
__global__ void pool_norm_kernel(const float* __restrict__ src,
                                 const float* __restrict__ cw,   // (3,3,1,64)
                                 const float* __restrict__ gam,  // (64)
                                 const float* __restrict__ bet,  // (64)
                                 float* __restrict__ dst) {
    int n    = blockIdx.x;   // 0..196 output token
    int bt   = blockIdx.y;   // 0..15
    int h    = blockIdx.z;   // 0..11
    int lane = threadIdx.x;  // 0..31
    int c0 = lane, c1 = lane + 32;

    float v0, v1;
    if (n == 0) {
        const float* p = src + ((size_t)bt * NTOK) * CC + h * HD;
        v0 = p[c0]; v1 = p[c1];
    } else {
        int io = (n - 1) / HP, jo = (n - 1) % HP;
        v0 = 0.f; v1 = 0.f;
        #pragma unroll
        for (int di = 0; di < 3; ++di) {
            int ii = 2 * io - 1 + di;
            if (ii < 0 || ii >= HH) continue;
            #pragma unroll
            for (int dj = 0; dj < 3; ++dj) {
                int jj = 2 * jo - 1 + dj;
                if (jj < 0 || jj >= WW) continue;
                const float* p = src + ((size_t)bt * NTOK + 1 + ii * WW + jj) * CC + h * HD;
                v0 += p[c0] * cw[(di * 3 + dj) * HD + c0];
                v1 += p[c1] * cw[(di * 3 + dj) * HD + c1];
            }
        }
    }
    float s = v0 + v1;
    #pragma unroll
    for (int off = 16; off > 0; off >>= 1) s += __shfl_xor_sync(0xffffffffu, s, off);
    float mu = s * (1.f / 64.f);
    float d0 = v0 - mu, d1 = v1 - mu;
    float vs = d0 * d0 + d1 * d1;
    #pragma unroll
    for (int off = 16; off > 0; off >>= 1) vs += __shfl_xor_sync(0xffffffffu, vs, off);
    float inv = rsqrtf(vs * (1.f / 64.f) + EPSLN);

    float* o = dst + ((size_t)bt * NQ + n) * CC + h * HD;
    o[c0] = d0 * inv * gam[c0] + bet[c0];
    o[c1] = d1 * inv * gam[c1] + bet[c1];
}

// ---------------------------------------------------------------------------
// Kernel 2: TF32 tensor-core GEMM  C[M,768] = A[M,768] @ W[768,768]^T
// 128x128 block, 8 warps (2x4), 64x32 per warp, k-chunk 32.
// MODE 0: scatter to (b, head, l, d);  MODE 1: row-major + bias.
// ---------------------------------------------------------------------------
#define SPAD 133   // smem row pad (k-major): conflict-free STS, <=2-way frag LDS

template<int MODE>
__global__ __launch_bounds__(256, 1)
void mma_gemm_kernel(const float* __restrict__ A, const float* __restrict__ W,
                     const float* __restrict__ bias, float* __restrict__ C,
                     int M) {
    __shared__ float As[32 * SPAD];
    __shared__ float Bs[32 * SPAD];

    const int tid  = threadIdx.x;
    const int lane = tid & 31;
    const int warp = tid >> 5;
    const int gid  = lane >> 2;   // 0..7
    const int tig  = lane & 3;    // 0..3
    const int wm   = warp >> 2;   // 0..1  (64-row slab)
    const int wn   = warp & 3;    // 0..3  (32-col slab)
    const int row0 = blockIdx.y * 128;
    const int col0 = blockIdx.x * 128;

    float acc[4][4][4];
    #pragma unroll
    for (int mt = 0; mt < 4; mt++)
        #pragma unroll
        for (int nt = 0; nt < 4; nt++)
            #pragma unroll
            for (int i = 0; i < 4; i++) acc[mt][nt][i] = 0.f;

    // loader mapping: 1024 float4 per matrix per chunk; 4 per thread
    int lrow[4], lc4[4];
    #pragma unroll
    for (int i = 0; i < 4; i++) {
        int idx = i * 256 + tid;
        lrow[i] = idx >> 3;
        lc4[i]  = (idx & 7) * 4;
    }

    float4 ra[4], rb[4];
    // prefetch chunk 0
    #pragma unroll
    for (int i = 0; i < 4; i++) {
        int r = row0 + lrow[i];
        ra[i] = (r < M) ? *(const float4*)(A + (size_t)r * 768 + lc4[i])
                        : make_float4(0.f, 0.f, 0.f, 0.f);
        rb[i] = *(const float4*)(W + (size_t)(col0 + lrow[i]) * 768 + lc4[i]);
    }

    for (int chunk = 0; chunk < 24; chunk++) {
        // store staged regs to smem (tf32-rounded), k-major
        #pragma unroll
        for (int i = 0; i < 4; i++) {
            int k = lc4[i], m = lrow[i];
            As[(k + 0) * SPAD + m] = f2tff(ra[i].x);
            As[(k + 1) * SPAD + m] = f2tff(ra[i].y);
            As[(k + 2) * SPAD + m] = f2tff(ra[i].z);
            As[(k + 3) * SPAD + m] = f2tff(ra[i].w);
            Bs[(k + 0) * SPAD + m] = f2tff(rb[i].x);
            Bs[(k + 1) * SPAD + m] = f2tff(rb[i].y);
            Bs[(k + 2) * SPAD + m] = f2tff(rb[i].z);
            Bs[(k + 3) * SPAD + m] = f2tff(rb[i].w);
        }
        __syncthreads();

        if (chunk < 23) {
            int kc = (chunk + 1) * 32;
            #pragma unroll
            for (int i = 0; i < 4; i++) {
                int r = row0 + lrow[i];
                ra[i] = (r < M) ? *(const float4*)(A + (size_t)r * 768 + kc + lc4[i])
                                : make_float4(0.f, 0.f, 0.f, 0.f);
                rb[i] = *(const float4*)(W + (size_t)(col0 + lrow[i]) * 768 + kc + lc4[i]);
            }
        }

        #pragma unroll
        for (int ks = 0; ks < 4; ks++) {
            int k0 = ks * 8;
            uint32_t af[4][4], bf[4][2];
            #pragma unroll
            for (int mt = 0; mt < 4; mt++) {
                int m = wm * 64 + mt * 16 + gid;
                af[mt][0] = __float_as_uint(As[(k0 + tig) * SPAD + m]);
                af[mt][1] = __float_as_uint(As[(k0 + tig) * SPAD + m + 8]);
                af[mt][2] = __float_as_uint(As[(k0 + tig + 4) * SPAD + m]);
                af[mt][3] = __float_as_uint(As[(k0 + tig + 4) * SPAD + m + 8]);
            }
            #pragma unroll
            for (int nt = 0; nt < 4; nt++) {
                int n = wn * 32 + nt * 8 + gid;
                bf[nt][0] = __float_as_uint(Bs[(k0 + tig) * SPAD + n]);
                bf[nt][1] = __float_as_uint(Bs[(k0 + tig + 4) * SPAD + n]);
            }
            #pragma unroll
            for (int mt = 0; mt < 4; mt++)
                #pragma unroll
                for (int nt = 0; nt < 4; nt++)
                    mma_tf32(acc[mt][nt], af[mt], bf[nt]);
        }
        __syncthreads();
    }

    // epilogue
    #pragma unroll
    for (int mt = 0; mt < 4; mt++) {
        #pragma unroll
        for (int rr = 0; rr < 2; rr++) {
            int m = row0 + wm * 64 + mt * 16 + gid + rr * 8;
            if (m >= M) continue;
            #pragma unroll
            for (int nt = 0; nt < 4; nt++) {
                int n = col0 + wn * 32 + nt * 8 + 2 * tig;
                float c0 = acc[mt][nt][rr * 2 + 0];
                float c1 = acc[mt][nt][rr * 2 + 1];
                if (MODE == 0) {
                    int b = m / LSEQ, l = m % LSEQ;
                    size_t o = (((size_t)(b * NHEAD + (n >> 6)) * LSEQ + l) << 6) + (n & 63);
                    *(float2*)(C + o) = make_float2(c0, c1);
                } else {
                    *(float2*)(C + (size_t)m * 768 + n) =
                        make_float2(c0 + bias[n], c1 + bias[n + 1]);
                }
            }
        }
    }
}

// ---------------------------------------------------------------------------
// Kernel 3: TF32 flash attention. Block = (bh, 64-query tile), 4 warps,
// 16 query rows per warp, 64-key tiles. Q frags in regs; K/V staged tf32 in
// smem; P re-fragmented through per-warp smem (aliased over Ks).
// Output to (b*l, C) with fused Q residual (skipped for l==0).
// ---------------------------------------------------------------------------
#define KPAD 68
#define VPAD 72

__global__ __launch_bounds__(128, 1)
void flash_mma_kernel(const float* __restrict__ Q, const float* __restrict__ Kp,
                      const float* __restrict__ Vp, float* __restrict__ O) {
    __shared__ float Ks[64 * KPAD];   // also P scratch: warp w uses Ks + w*16*KPAD
    __shared__ float Vs[64 * VPAD];

    const int tid  = threadIdx.x;
    const int lane = tid & 31;
    const int wid  = tid >> 5;   // 0..3
    const int gid  = lane >> 2;  // 0..7
    const int tig  = lane & 3;   // 0..3
    const int bh   = blockIdx.y;
    const int b    = bh / NHEAD;
    const int h    = bh % NHEAD;
    const int qrow0 = blockIdx.x * 64 + wid * 16;

    const float* Qb = Q + (size_t)bh * LSEQ * HD;
    const float* Kb = Kp + (size_t)bh * LSEQ * HD;
    const float* Vb = Vp + (size_t)bh * LSEQ * HD;

    // Q fragments (scaled by hd^-0.5 = 1/8), tf32-rounded, held in registers
    uint32_t qf[8][4];
    {
        int rl = min(qrow0 + gid, LSEQ - 1);
        int rh = min(qrow0 + gid + 8, LSEQ - 1);
        #pragma unroll
        for (int ks = 0; ks < 8; ks++) {
            qf[ks][0] = f2tf(0.125f * Qb[(size_t)rl * HD + ks * 8 + tig]);
            qf[ks][1] = f2tf(0.125f * Qb[(size_t)rh * HD + ks * 8 + tig]);
            qf[ks][2] = f2tf(0.125f * Qb[(size_t)rl * HD + ks * 8 + tig + 4]);
            qf[ks][3] = f2tf(0.125f * Qb[(size_t)rh * HD + ks * 8 + tig + 4]);
        }
    }

    float off[8][4];
    #pragma unroll
    for (int nt = 0; nt < 8; nt++)
        #pragma unroll
        for (int i = 0; i < 4; i++) off[nt][i] = 0.f;
    float m0 = -1e30f, m1 = -1e30f, l0 = 0.f, l1 = 0.f;

    float* Ps = Ks + wid * 16 * KPAD;   // per-warp 16x64 P scratch (aliases Ks)

    for (int kt0 = 0; kt0 < LSEQ; kt0 += 64) {
        // stage K,V tile (tf32-rounded); clamp rows, mask handles validity
        #pragma unroll
        for (int i = 0; i < 8; i++) {
            int idx = i * 128 + tid;
            int r = idx >> 4, c4 = (idx & 15) * 4;
            int key = min(kt0 + r, LSEQ - 1);
            float4 kv = *(const float4*)(Kb + (size_t)key * HD + c4);
            float4 vv = *(const float4*)(Vb + (size_t)key * HD + c4);
            *(float4*)(Ks + r * KPAD + c4) =
                make_float4(f2tff(kv.x), f2tff(kv.y), f2tff(kv.z), f2tff(kv.w));
            *(float4*)(Vs + r * VPAD + c4) =
                make_float4(f2tff(vv.x), f2tff(vv.y), f2tff(vv.z), f2tff(vv.w));
        }
        __syncthreads();

        // S = Q K^T  (64 mma per warp)
        float sf[8][4];
        #pragma unroll
        for (int nt = 0; nt < 8; nt++)
            #pragma unroll
            for (int i = 0; i < 4; i++) sf[nt][i] = 0.f;

        #pragma unroll
        for (int nt = 0; nt < 8; nt++) {
            const float* krow = Ks + (nt * 8 + gid) * KPAD;
            #pragma unroll
            for (int ks = 0; ks < 8; ks++) {
                uint32_t bf[2];
                bf[0] = __float_as_uint(krow[ks * 8 + tig]);
                bf[1] = __float_as_uint(krow[ks * 8 + tig + 4]);
                mma_tf32(sf[nt], qf[ks], bf);
            }
        }
        __syncthreads();   // everyone done reading Ks before Ps overwrite

        // mask invalid keys (last tile)
        if (kt0 + 64 > LSEQ) {
            #pragma unroll
            for (int nt = 0; nt < 8; nt++) {
                int c = kt0 + nt * 8 + 2 * tig;
                if (c >= LSEQ)     { sf[nt][0] = -1e30f; sf[nt][2] = -1e30f; }
                if (c + 1 >= LSEQ) { sf[nt][1] = -1e30f; sf[nt][3] = -1e30f; }
            }
        }

        // online softmax (rows gid, gid+8)
        float rmax0 = -1e30f, rmax1 = -1e30f;
        #pragma unroll
        for (int nt = 0; nt < 8; nt++) {
            rmax0 = fmaxf(rmax0, fmaxf(sf[nt][0], sf[nt][1]));
            rmax1 = fmaxf(rmax1, fmaxf(sf[nt][2], sf[nt][3]));
        }
        #pragma unroll
        for (int o = 1; o <= 2; o <<= 1) {
            rmax0 = fmaxf(rmax0, __shfl_xor_sync(0xffffffffu, rmax0, o));
            rmax1 = fmaxf(rmax1, __shfl_xor_sync(0xffffffffu, rmax1, o));
        }
        float mn0 = fmaxf(m0, rmax0), mn1 = fmaxf(m1, rmax1);
        float sc0 = __expf(m0 - mn0), sc1 = __expf(m1 - mn1);
        m0 = mn0; m1 = mn1;

        float rs0 = 0.f, rs1 = 0.f;
        #pragma unroll
        for (int nt = 0; nt < 8; nt++) {
            float p0 = __expf(sf[nt][0] - m0);
            float p1 = __expf(sf[nt][1] - m0);
            float p2 = __expf(sf[nt][2] - m1);
            float p3 = __expf(sf[nt][3] - m1);
            rs0 += p0 + p1; rs1 += p2 + p3;
            *(float2*)(Ps + gid * KPAD + nt * 8 + 2 * tig) =
                make_float2(f2tff(p0), f2tff(p1));
            *(float2*)(Ps + (gid + 8) * KPAD + nt * 8 + 2 * tig) =
                make_float2(f2tff(p2), f2tff(p3));
        }
        #pragma unroll
        for (int o = 1; o <= 2; o <<= 1) {
            rs0 += __shfl_xor_sync(0xffffffffu, rs0, o);
            rs1 += __shfl_xor_sync(0xffffffffu, rs1, o);
        }
        l0 = l0 * sc0 + rs0;
        l1 = l1 * sc1 + rs1;
        #pragma unroll
        for (int nt = 0; nt < 8; nt++) {
            off[nt][0] *= sc0; off[nt][1] *= sc0;
            off[nt][2] *= sc1; off[nt][3] *= sc1;
        }
        __syncwarp();

        // O += P V  (64 mma per warp)
        #pragma unroll
        for (int ks = 0; ks < 8; ks++) {
            uint32_t af[4];
            af[0] = __float_as_uint(Ps[gid * KPAD + ks * 8 + tig]);
            af[1] = __float_as_uint(Ps[(gid + 8) * KPAD + ks * 8 + tig]);
            af[2] = __float_as_uint(Ps[gid * KPAD + ks * 8 + tig + 4]);
            af[3] = __float_as_uint(Ps[(gid + 8) * KPAD + ks * 8 + tig + 4]);
            #pragma unroll
            for (int nt = 0; nt < 8; nt++) {
                uint32_t bf[2];
                bf[0] = __float_as_uint(Vs[(ks * 8 + tig) * VPAD + nt * 8 + gid]);
                bf[1] = __float_as_uint(Vs[(ks * 8 + tig + 4) * VPAD + nt * 8 + gid]);
                mma_tf32(off[nt], af, bf);
            }
        }
        __syncthreads();
    }

    // epilogue: O/l + Q residual (l != 0), scatter to (b*l, C)
    float inv0 = 1.f / l0, inv1 = 1.f / l1;
    #pragma unroll
    for (int rr = 0; rr < 2; rr++) {
        int row = qrow0 + gid + rr * 8;
        if (row >= LSEQ) continue;
        float inv = rr ? inv1 : inv0;
        float resid = (row != 0) ? 1.f : 0.f;
        float* op = O + ((size_t)(b * LSEQ + row)) * CC + h * HD;
        #pragma unroll
        for (int nt = 0; nt < 8; nt++) {
            int c = nt * 8 + 2 * tig;
            float2 qv = *(const float2*)(Qb + (size_t)row * HD + c);
            float v0 = off[nt][rr * 2 + 0] * inv + resid * qv.x;
            float v1 = off[nt][rr * 2 + 1] * inv + resid * qv.y;
            *(float2*)(op + c) = make_float2(v0, v1);
        }
    }
}

// ---------------------------------------------------------------------------
extern "C" void kernel_launch(void* const* d_in, const int* in_sizes, int n_in,
                              void* d_out, int out_size) {
    const float* x  = (const float*)d_in[0];
    const float* xr = (const float*)d_in[1];
    const float* wq = (const float*)d_in[2];
    const float* wk = (const float*)d_in[3];
    const float* wv = (const float*)d_in[4];
    const float* wp = (const float*)d_in[5];
    const float* bp = (const float*)d_in[6];
    const float* cq = (const float*)d_in[7];
    const float* ck = (const float*)d_in[8];
    const float* cv = (const float*)d_in[9];
    const float* gq = (const float*)d_in[10];
    const float* bq = (const float*)d_in[11];
    const float* gk = (const float*)d_in[12];
    const float* bk = (const float*)d_in[13];
    const float* gv = (const float*)d_in[14];
    const float* bv = (const float*)d_in[15];
    float* out = (float*)d_out;

    float *pq, *pk, *pv, *qd, *kd, *vd, *ao;
    cudaGetSymbolAddress((void**)&pq, g_poolq);
    cudaGetSymbolAddress((void**)&pk, g_poolk);
    cudaGetSymbolAddress((void**)&pv, g_poolv);
    cudaGetSymbolAddress((void**)&qd, g_q);
    cudaGetSymbolAddress((void**)&kd, g_k);
    cudaGetSymbolAddress((void**)&vd, g_v);
    cudaGetSymbolAddress((void**)&ao, g_ao);

    dim3 pg(NQ, BT, NHEAD);
    pool_norm_kernel<<<pg, 32>>>(x,  cq, gq, bq, pq);
    pool_norm_kernel<<<pg, 32>>>(xr, ck, gk, bk, pk);
    pool_norm_kernel<<<pg, 32>>>(xr, cv, gv, bv, pv);

    dim3 gg(CC / 128, (MROWS + 127) / 128);
    mma_gemm_kernel<0><<<gg, 256>>>(pq, wq, nullptr, qd, MROWS);
    mma_gemm_kernel<0><<<gg, 256>>>(pk, wk, nullptr, kd, MROWS);
    mma_gemm_kernel<0><<<gg, 256>>>(pv, wv, nullptr, vd, MROWS);

    dim3 fg((LSEQ + 63) / 64, BATCH * NHEAD);
    flash_mma_kernel<<<fg, 128>>>(qd, kd, vd, ao);

    mma_gemm_kernel<1><<<gg, 256>>>(ao, wp, bp, out, MROWS);
}

// round 4
// speedup vs baseline: 4.2859x; 1.2199x over previous
#include <cuda_runtime.h>
#include <math.h>
#include <stdint.h>

// Problem constants (fixed by reference setup_inputs)
#define BATCH 2
#define TT    8
#define HH    28
#define WW    28
#define CC    768
#define NHEAD 12
#define HD    64
#define NTOK  785        // 1 + 28*28
#define HP    14
#define NQ    197        // 1 + 14*14
#define BT    (BATCH*TT) // 16
#define MROWS (BT*CC/CC*NQ) // 3152
#define LSEQ  (TT*NQ)    // 1576
#define EPSLN 1e-5f

// Scratch (static device globals; no runtime allocation allowed)
__device__ float g_poolq[BT*NQ*CC];
__device__ float g_poolk[BT*NQ*CC];
__device__ float g_poolv[BT*NQ*CC];
__device__ float g_q[BT*NQ*CC];   // (b, h, l, d) layout
__device__ float g_k[BT*NQ*CC];
__device__ float g_v[BT*NQ*CC];
__device__ float g_ao[BT*NQ*CC];  // (b*L, C) layout

#define MR (BT*NQ)   // 3152 rows for GEMMs

// ---------------------------------------------------------------------------
// helpers: tf32 convert + mma + cp.async
// ---------------------------------------------------------------------------
__device__ __forceinline__ uint32_t f2tf(float x) {
    uint32_t r;
    asm("cvt.rna.tf32.f32 %0, %1;" : "=r"(r) : "f"(x));
    return r;
}
__device__ __forceinline__ float f2tff(float x) {
    return __uint_as_float(f2tf(x));
}
__device__ __forceinline__ void mma_tf32(float* d, const uint32_t* a, const uint32_t* b) {
    asm volatile(
        "mma.sync.aligned.m16n8k8.row.col.f32.tf32.tf32.f32 "
        "{%0,%1,%2,%3}, {%4,%5,%6,%7}, {%8,%9}, {%0,%1,%2,%3};\n"
        : "+f"(d[0]), "+f"(d[1]), "+f"(d[2]), "+f"(d[3])
        : "r"(a[0]), "r"(a[1]), "r"(a[2]), "r"(a[3]), "r"(b[0]), "r"(b[1]));
}
__device__ __forceinline__ void cp16(float* s, const float* g, bool valid) {
    uint32_t sa = (uint32_t)__cvta_generic_to_shared(s);
    int sz = valid ? 16 : 0;
    asm volatile("cp.async.cg.shared.global [%0], [%1], 16, %2;\n"
                 :: "r"(sa), "l"(g), "r"(sz));
}
__device__ __forceinline__ void cp_commit() {
    asm volatile("cp.async.commit_group;\n");
}
template<int N>
__device__ __forceinline__ void cp_wait() {
    asm volatile("cp.async.wait_group %0;\n" :: "n"(N));
}

// ---------------------------------------------------------------------------
// Kernel 1a: pool+LN for Q. One warp per (bt, token, head).
// ---------------------------------------------------------------------------
__device__ __forceinline__ void pool_core(const float* __restrict__ src,
                                          const float* __restrict__ cw,
                                          int n, int bt, int h, int c0, int c1,
                                          float& v0, float& v1) {
    if (n == 0) {
        const float* p = src + ((size_t)bt * NTOK) * CC + h * HD;
        v0 = p[c0]; v1 = p[c1];
    } else {
        int io = (n - 1) / HP, jo = (n - 1) % HP;
        v0 = 0.f; v1 = 0.f;
        #pragma unroll
        for (int di = 0; di < 3; ++di) {
            int ii = 2 * io - 1 + di;
            if (ii < 0 || ii >= HH) continue;
            #pragma unroll
            for (int dj = 0; dj < 3; ++dj) {
                int jj = 2 * jo - 1 + dj;
                if (jj < 0 || jj >= WW) continue;
                const float* p = src + ((size_t)bt * NTOK + 1 + ii * WW + jj) * CC + h * HD;
                v0 += p[c0] * cw[(di * 3 + dj) * HD + c0];
                v1 += p[c1] * cw[(di * 3 + dj) * HD + c1];
            }
        }
    }
}

__device__ __forceinline__ void ln_store(float v0, float v1,
                                         const float* __restrict__ gam,
                                         const float* __restrict__ bet,
                                         float* __restrict__ o, int c0, int c1) {
    float s = v0 + v1;
    #pragma unroll
    for (int off = 16; off > 0; off >>= 1) s += __shfl_xor_sync(0xffffffffu, s, off);
    float mu = s * (1.f / 64.f);
    float d0 = v0 - mu, d1 = v1 - mu;
    float vs = d0 * d0 + d1 * d1;
    #pragma unroll
    for (int off = 16; off > 0; off >>= 1) vs += __shfl_xor_sync(0xffffffffu, vs, off);
    float inv = rsqrtf(vs * (1.f / 64.f) + EPSLN);
    o[c0] = d0 * inv * gam[c0] + bet[c0];
    o[c1] = d1 * inv * gam[c1] + bet[c1];
}

__global__ void pool_norm_kernel(const float* __restrict__ src,
                                 const float* __restrict__ cw,
                                 const float* __restrict__ gam,
                                 const float* __restrict__ bet,
                                 float* __restrict__ dst) {
    int n = blockIdx.x, bt = blockIdx.y, h = blockIdx.z;
    int lane = threadIdx.x, c0 = lane, c1 = lane + 32;
    float v0, v1;
    pool_core(src, cw, n, bt, h, c0, c1, v0, v1);
    float* o = dst + ((size_t)bt * NQ + n) * CC + h * HD;
    ln_store(v0, v1, gam, bet, o, c0, c1);
}

// Kernel 1b: fused K+V pools (xr read once)
__global__ void pool_norm_dual_kernel(const float* __restrict__ src,
                                      const float* __restrict__ cwk,
                                      const float* __restrict__ gk,
                                      const float* __restrict__ bk,
                                      float* __restrict__ dk,
                                      const float* __restrict__ cwv,
                                      const float* __restrict__ gv,
                                      const float* __restrict__ bv,
                                      float* __restrict__ dv) {
    int n = blockIdx.x, bt = blockIdx.y, h = blockIdx.z;
    int lane = threadIdx.x, c0 = lane, c1 = lane + 32;
    float k0, k1, v0, v1;
    if (n == 0) {
        const float* p = src + ((size_t)bt * NTOK) * CC + h * HD;
        k0 = v0 = p[c0]; k1 = v1 = p[c1];
    } else {
        int io = (n - 1) / HP, jo = (n - 1) % HP;
        k0 = k1 = v0 = v1 = 0.f;
        #pragma unroll
        for (int di = 0; di < 3; ++di) {
            int ii = 2 * io - 1 + di;
            if (ii < 0 || ii >= HH) continue;
            #pragma unroll
            for (int dj = 0; dj < 3; ++dj) {
                int jj = 2 * jo - 1 + dj;
                if (jj < 0 || jj >= WW) continue;
                const float* p = src + ((size_t)bt * NTOK + 1 + ii * WW + jj) * CC + h * HD;
                float a0 = p[c0], a1 = p[c1];
                int wi = (di * 3 + dj) * HD;
                k0 += a0 * cwk[wi + c0]; k1 += a1 * cwk[wi + c1];
                v0 += a0 * cwv[wi + c0]; v1 += a1 * cwv[wi + c1];
            }
        }
    }
    size_t ob = ((size_t)bt * NQ + n) * CC + h * HD;
    ln_store(k0, k1, gk, bk, dk + ob, c0, c1);
    ln_store(v0, v1, gv, bv, dv + ob, c0, c1);
}

// ---------------------------------------------------------------------------
// Kernel 2: TF32 tensor-core GEMM  C[M,768] = A[M,768] @ W[768,768]^T
// 128x128 block, 8 warps (2x4), cp.async double-buffered, k-chunk 32.
// smem m-major [row][36]. tf32 cvt at fragment load (rna).
// MODE 0: scatter to (b, head, l, d);  MODE 1: row-major + bias.
// ---------------------------------------------------------------------------
#define GROW 36              // 32 k + 4 pad (conflict-free frag loads)
#define GBUF (128*GROW)      // floats per matrix per buffer

template<int MODE>
__global__ __launch_bounds__(256, 2)
void mma_gemm_kernel(const float* __restrict__ A, const float* __restrict__ W,
                     const float* __restrict__ bias, float* __restrict__ C,
                     int M) {
    extern __shared__ float sm[];
    float* As = sm;              // [2][128][GROW]
    float* Bs = sm + 2 * GBUF;   // [2][128][GROW]

    const int tid  = threadIdx.x;
    const int lane = tid & 31;
    const int warp = tid >> 5;
    const int gid  = lane >> 2;
    const int tig  = lane & 3;
    const int wm   = warp >> 2;   // 0..1
    const int wn   = warp & 3;    // 0..3
    const int row0 = blockIdx.y * 128;
    const int col0 = blockIdx.x * 128;

    float acc[4][4][4];
    #pragma unroll
    for (int mt = 0; mt < 4; mt++)
        #pragma unroll
        for (int nt = 0; nt < 4; nt++)
            #pragma unroll
            for (int i = 0; i < 4; i++) acc[mt][nt][i] = 0.f;

    // copy lambda: 4 float4 per thread per matrix per chunk
    auto copy_chunk = [&](int chunk, int p) {
        int kc = chunk * 32;
        #pragma unroll
        for (int i = 0; i < 4; i++) {
            int idx = i * 256 + tid;
            int r = idx >> 3, c4 = (idx & 7) * 4;
            int ar = row0 + r;
            bool av = ar < M;
            cp16(As + p * GBUF + r * GROW + c4,
                 A + (size_t)(av ? ar : 0) * 768 + kc + c4, av);
            cp16(Bs + p * GBUF + r * GROW + c4,
                 W + (size_t)(col0 + r) * 768 + kc + c4, true);
        }
    };

    copy_chunk(0, 0);
    cp_commit();

    int p = 0;
    for (int chunk = 0; chunk < 24; chunk++) {
        if (chunk < 23) {
            copy_chunk(chunk + 1, p ^ 1);
            cp_commit();
            cp_wait<1>();
        } else {
            cp_wait<0>();
        }
        __syncthreads();

        const float* Ab = As + p * GBUF;
        const float* Bb = Bs + p * GBUF;
        #pragma unroll
        for (int ks = 0; ks < 4; ks++) {
            int k0 = ks * 8;
            uint32_t af[4][4], bf[4][2];
            #pragma unroll
            for (int mt = 0; mt < 4; mt++) {
                int m = wm * 64 + mt * 16 + gid;
                af[mt][0] = f2tf(Ab[(m    ) * GROW + k0 + tig]);
                af[mt][1] = f2tf(Ab[(m + 8) * GROW + k0 + tig]);
                af[mt][2] = f2tf(Ab[(m    ) * GROW + k0 + tig + 4]);
                af[mt][3] = f2tf(Ab[(m + 8) * GROW + k0 + tig + 4]);
            }
            #pragma unroll
            for (int nt = 0; nt < 4; nt++) {
                int n = wn * 32 + nt * 8 + gid;
                bf[nt][0] = f2tf(Bb[n * GROW + k0 + tig]);
                bf[nt][1] = f2tf(Bb[n * GROW + k0 + tig + 4]);
            }
            #pragma unroll
            for (int mt = 0; mt < 4; mt++)
                #pragma unroll
                for (int nt = 0; nt < 4; nt++)
                    mma_tf32(acc[mt][nt], af[mt], bf[nt]);
        }
        __syncthreads();
        p ^= 1;
    }

    // epilogue
    #pragma unroll
    for (int mt = 0; mt < 4; mt++) {
        #pragma unroll
        for (int rr = 0; rr < 2; rr++) {
            int m = row0 + wm * 64 + mt * 16 + gid + rr * 8;
            if (m >= M) continue;
            #pragma unroll
            for (int nt = 0; nt < 4; nt++) {
                int n = col0 + wn * 32 + nt * 8 + 2 * tig;
                float c0 = acc[mt][nt][rr * 2 + 0];
                float c1 = acc[mt][nt][rr * 2 + 1];
                if (MODE == 0) {
                    int b = m / LSEQ, l = m % LSEQ;
                    size_t o = (((size_t)(b * NHEAD + (n >> 6)) * LSEQ + l) << 6) + (n & 63);
                    *(float2*)(C + o) = make_float2(c0, c1);
                } else {
                    *(float2*)(C + (size_t)m * 768 + n) =
                        make_float2(c0 + bias[n], c1 + bias[n + 1]);
                }
            }
        }
    }
}

// ---------------------------------------------------------------------------
// Kernel 3: TF32 flash attention, cp.async double-buffered K/V, separate Ps.
// Block = (bh, 64-query tile), 4 warps, 16 rows/warp, 64-key tiles.
// ---------------------------------------------------------------------------
#define KPAD 68
#define VPAD 72
#define KTILE_F (64*KPAD)
#define VTILE_F (64*VPAD)

__global__ __launch_bounds__(128, 2)
void flash_mma_kernel(const float* __restrict__ Q, const float* __restrict__ Kp,
                      const float* __restrict__ Vp, float* __restrict__ O) {
    extern __shared__ float sm[];
    float* Ks = sm;                                   // [2][64][KPAD]
    float* Vs = sm + 2 * KTILE_F;                     // [2][64][VPAD]
    float* Pa = sm + 2 * KTILE_F + 2 * VTILE_F;       // [4][16][KPAD]

    const int tid  = threadIdx.x;
    const int lane = tid & 31;
    const int wid  = tid >> 5;
    const int gid  = lane >> 2;
    const int tig  = lane & 3;
    const int bh   = blockIdx.y;
    const int b    = bh / NHEAD;
    const int h    = bh % NHEAD;
    const int qrow0 = blockIdx.x * 64 + wid * 16;

    const float* Qb = Q + (size_t)bh * LSEQ * HD;
    const float* Kb = Kp + (size_t)bh * LSEQ * HD;
    const float* Vb = Vp + (size_t)bh * LSEQ * HD;

    // Q fragments (scaled by 1/8), tf32-rounded, in registers
    uint32_t qf[8][4];
    {
        int rl = min(qrow0 + gid, LSEQ - 1);
        int rh = min(qrow0 + gid + 8, LSEQ - 1);
        #pragma unroll
        for (int ks = 0; ks < 8; ks++) {
            qf[ks][0] = f2tf(0.125f * Qb[(size_t)rl * HD + ks * 8 + tig]);
            qf[ks][1] = f2tf(0.125f * Qb[(size_t)rh * HD + ks * 8 + tig]);
            qf[ks][2] = f2tf(0.125f * Qb[(size_t)rl * HD + ks * 8 + tig + 4]);
            qf[ks][3] = f2tf(0.125f * Qb[(size_t)rh * HD + ks * 8 + tig + 4]);
        }
    }

    float off[8][4];
    #pragma unroll
    for (int nt = 0; nt < 8; nt++)
        #pragma unroll
        for (int i = 0; i < 4; i++) off[nt][i] = 0.f;
    float m0 = -1e30f, m1 = -1e30f, l0 = 0.f, l1 = 0.f;

    float* Ps = Pa + wid * 16 * KPAD;

    auto copy_tile = [&](int t, int p) {
        int kt0 = t * 64;
        #pragma unroll
        for (int i = 0; i < 8; i++) {
            int idx = i * 128 + tid;
            int r = idx >> 4, c4 = (idx & 15) * 4;
            bool v = kt0 + r < LSEQ;
            int key = v ? (kt0 + r) : 0;
            cp16(Ks + p * KTILE_F + r * KPAD + c4, Kb + (size_t)key * HD + c4, v);
            cp16(Vs + p * VTILE_F + r * VPAD + c4, Vb + (size_t)key * HD + c4, v);
        }
    };

    const int NT = (LSEQ + 63) / 64;   // 25
    copy_tile(0, 0);
    cp_commit();

    int p = 0;
    for (int t = 0; t < NT; t++) {
        if (t < NT - 1) {
            copy_tile(t + 1, p ^ 1);
            cp_commit();
            cp_wait<1>();
        } else {
            cp_wait<0>();
        }
        __syncthreads();

        const float* Kt = Ks + p * KTILE_F;
        const float* Vt = Vs + p * VTILE_F;
        int kt0 = t * 64;

        // S = Q K^T
        float sf[8][4];
        #pragma unroll
        for (int nt = 0; nt < 8; nt++)
            #pragma unroll
            for (int i = 0; i < 4; i++) sf[nt][i] = 0.f;

        #pragma unroll
        for (int nt = 0; nt < 8; nt++) {
            const float* krow = Kt + (nt * 8 + gid) * KPAD;
            #pragma unroll
            for (int ks = 0; ks < 8; ks++) {
                uint32_t bf[2];
                bf[0] = f2tf(krow[ks * 8 + tig]);
                bf[1] = f2tf(krow[ks * 8 + tig + 4]);
                mma_tf32(sf[nt], qf[ks], bf);
            }
        }

        // mask invalid keys (last tile; zero-filled rows)
        if (kt0 + 64 > LSEQ) {
            #pragma unroll
            for (int nt = 0; nt < 8; nt++) {
                int c = kt0 + nt * 8 + 2 * tig;
                if (c >= LSEQ)     { sf[nt][0] = -1e30f; sf[nt][2] = -1e30f; }
                if (c + 1 >= LSEQ) { sf[nt][1] = -1e30f; sf[nt][3] = -1e30f; }
            }
        }

        // online softmax (rows gid, gid+8)
        float rmax0 = -1e30f, rmax1 = -1e30f;
        #pragma unroll
        for (int nt = 0; nt < 8; nt++) {
            rmax0 = fmaxf(rmax0, fmaxf(sf[nt][0], sf[nt][1]));
            rmax1 = fmaxf(rmax1, fmaxf(sf[nt][2], sf[nt][3]));
        }
        #pragma unroll
        for (int o = 1; o <= 2; o <<= 1) {
            rmax0 = fmaxf(rmax0, __shfl_xor_sync(0xffffffffu, rmax0, o));
            rmax1 = fmaxf(rmax1, __shfl_xor_sync(0xffffffffu, rmax1, o));
        }
        float mn0 = fmaxf(m0, rmax0), mn1 = fmaxf(m1, rmax1);
        float sc0 = __expf(m0 - mn0), sc1 = __expf(m1 - mn1);
        m0 = mn0; m1 = mn1;

        float rs0 = 0.f, rs1 = 0.f;
        #pragma unroll
        for (int nt = 0; nt < 8; nt++) {
            float p0 = __expf(sf[nt][0] - m0);
            float p1 = __expf(sf[nt][1] - m0);
            float p2 = __expf(sf[nt][2] - m1);
            float p3 = __expf(sf[nt][3] - m1);
            rs0 += p0 + p1; rs1 += p2 + p3;
            *(float2*)(Ps + gid * KPAD + nt * 8 + 2 * tig) =
                make_float2(f2tff(p0), f2tff(p1));
            *(float2*)(Ps + (gid + 8) * KPAD + nt * 8 + 2 * tig) =
                make_float2(f2tff(p2), f2tff(p3));
        }
        #pragma unroll
        for (int o = 1; o <= 2; o <<= 1) {
            rs0 += __shfl_xor_sync(0xffffffffu, rs0, o);
            rs1 += __shfl_xor_sync(0xffffffffu, rs1, o);
        }
        l0 = l0 * sc0 + rs0;
        l1 = l1 * sc1 + rs1;
        #pragma unroll
        for (int nt = 0; nt < 8; nt++) {
            off[nt][0] *= sc0; off[nt][1] *= sc0;
            off[nt][2] *= sc1; off[nt][3] *= sc1;
        }
        __syncwarp();

        // O += P V
        #pragma unroll
        for (int ks = 0; ks < 8; ks++) {
            uint32_t af[4];
            af[0] = __float_as_uint(Ps[gid * KPAD + ks * 8 + tig]);
            af[1] = __float_as_uint(Ps[(gid + 8) * KPAD + ks * 8 + tig]);
            af[2] = __float_as_uint(Ps[gid * KPAD + ks * 8 + tig + 4]);
            af[3] = __float_as_uint(Ps[(gid + 8) * KPAD + ks * 8 + tig + 4]);
            #pragma unroll
            for (int nt = 0; nt < 8; nt++) {
                uint32_t bf[2];
                bf[0] = f2tf(Vt[(ks * 8 + tig) * VPAD + nt * 8 + gid]);
                bf[1] = f2tf(Vt[(ks * 8 + tig + 4) * VPAD + nt * 8 + gid]);
                mma_tf32(off[nt], af, bf);
            }
        }
        __syncthreads();
        p ^= 1;
    }

    // epilogue: O/l + Q residual (l != 0), scatter to (b*l, C)
    float inv0 = 1.f / l0, inv1 = 1.f / l1;
    #pragma unroll
    for (int rr = 0; rr < 2; rr++) {
        int row = qrow0 + gid + rr * 8;
        if (row >= LSEQ) continue;
        float inv = rr ? inv1 : inv0;
        float resid = (row != 0) ? 1.f : 0.f;
        float* op = O + ((size_t)(b * LSEQ + row)) * CC + h * HD;
        #pragma unroll
        for (int nt = 0; nt < 8; nt++) {
            int c = nt * 8 + 2 * tig;
            float2 qv = *(const float2*)(Qb + (size_t)row * HD + c);
            float v0 = off[nt][rr * 2 + 0] * inv + resid * qv.x;
            float v1 = off[nt][rr * 2 + 1] * inv + resid * qv.y;
            *(float2*)(op + c) = make_float2(v0, v1);
        }
    }
}

// ---------------------------------------------------------------------------
extern "C" void kernel_launch(void* const* d_in, const int* in_sizes, int n_in,
                              void* d_out, int out_size) {
    const float* x  = (const float*)d_in[0];
    const float* xr = (const float*)d_in[1];
    const float* wq = (const float*)d_in[2];
    const float* wk = (const float*)d_in[3];
    const float* wv = (const float*)d_in[4];
    const float* wp = (const float*)d_in[5];
    const float* bp = (const float*)d_in[6];
    const float* cq = (const float*)d_in[7];
    const float* ck = (const float*)d_in[8];
    const float* cv = (const float*)d_in[9];
    const float* gq = (const float*)d_in[10];
    const float* bq = (const float*)d_in[11];
    const float* gk = (const float*)d_in[12];
    const float* bk = (const float*)d_in[13];
    const float* gv = (const float*)d_in[14];
    const float* bv = (const float*)d_in[15];
    float* out = (float*)d_out;

    float *pq, *pk, *pv, *qd, *kd, *vd, *ao;
    cudaGetSymbolAddress((void**)&pq, g_poolq);
    cudaGetSymbolAddress((void**)&pk, g_poolk);
    cudaGetSymbolAddress((void**)&pv, g_poolv);
    cudaGetSymbolAddress((void**)&qd, g_q);
    cudaGetSymbolAddress((void**)&kd, g_k);
    cudaGetSymbolAddress((void**)&vd, g_v);
    cudaGetSymbolAddress((void**)&ao, g_ao);

    const int gemm_smem  = 4 * GBUF * (int)sizeof(float);                       // 73728
    const int flash_smem = (2 * KTILE_F + 2 * VTILE_F + 4 * 16 * KPAD) * (int)sizeof(float); // 89088
    cudaFuncSetAttribute(mma_gemm_kernel<0>, cudaFuncAttributeMaxDynamicSharedMemorySize, gemm_smem);
    cudaFuncSetAttribute(mma_gemm_kernel<1>, cudaFuncAttributeMaxDynamicSharedMemorySize, gemm_smem);
    cudaFuncSetAttribute(flash_mma_kernel,   cudaFuncAttributeMaxDynamicSharedMemorySize, flash_smem);

    dim3 pg(NQ, BT, NHEAD);
    pool_norm_kernel<<<pg, 32>>>(x, cq, gq, bq, pq);
    pool_norm_dual_kernel<<<pg, 32>>>(xr, ck, gk, bk, pk, cv, gv, bv, pv);

    dim3 gg(CC / 128, (MR + 127) / 128);
    mma_gemm_kernel<0><<<gg, 256, gemm_smem>>>(pq, wq, nullptr, qd, MR);
    mma_gemm_kernel<0><<<gg, 256, gemm_smem>>>(pk, wk, nullptr, kd, MR);
    mma_gemm_kernel<0><<<gg, 256, gemm_smem>>>(pv, wv, nullptr, vd, MR);

    dim3 fg((LSEQ + 63) / 64, BATCH * NHEAD);
    flash_mma_kernel<<<fg, 128, flash_smem>>>(qd, kd, vd, ao);

    mma_gemm_kernel<1><<<gg, 256, gemm_smem>>>(ao, wp, bp, out, MR);
}

// round 5
// speedup vs baseline: 4.8781x; 1.1382x over previous
#include <cuda_runtime.h>
#include <math.h>
#include <stdint.h>

// Problem constants (fixed by reference setup_inputs)
#define BATCH 2
#define TT    8
#define HH    28
#define WW    28
#define CC    768
#define NHEAD 12
#define HD    64
#define NTOK  785        // 1 + 28*28
#define HP    14
#define NQ    197        // 1 + 14*14
#define BT    (BATCH*TT) // 16
#define LSEQ  (TT*NQ)    // 1576
#define EPSLN 1e-5f
#define MR    (BT*NQ)    // 3152 rows for GEMMs

// Scratch (static device globals; no runtime allocation allowed)
__device__ float g_poolq[BT*NQ*CC];
__device__ float g_poolk[BT*NQ*CC];
__device__ float g_poolv[BT*NQ*CC];
__device__ float g_q[BT*NQ*CC];   // (b, h, l, d) layout
__device__ float g_k[BT*NQ*CC];
__device__ float g_v[BT*NQ*CC];
__device__ float g_ao[BT*NQ*CC];  // (b*L, C) layout

// ---------------------------------------------------------------------------
// helpers: tf32 convert + mma + cp.async
// ---------------------------------------------------------------------------
__device__ __forceinline__ uint32_t f2tf(float x) {
    uint32_t r;
    asm("cvt.rna.tf32.f32 %0, %1;" : "=r"(r) : "f"(x));
    return r;
}
__device__ __forceinline__ float f2tff(float x) {
    return __uint_as_float(f2tf(x));
}
__device__ __forceinline__ void mma_tf32(float* d, const uint32_t* a, const uint32_t* b) {
    asm volatile(
        "mma.sync.aligned.m16n8k8.row.col.f32.tf32.tf32.f32 "
        "{%0,%1,%2,%3}, {%4,%5,%6,%7}, {%8,%9}, {%0,%1,%2,%3};\n"
        : "+f"(d[0]), "+f"(d[1]), "+f"(d[2]), "+f"(d[3])
        : "r"(a[0]), "r"(a[1]), "r"(a[2]), "r"(a[3]), "r"(b[0]), "r"(b[1]));
}
__device__ __forceinline__ void cp16(float* s, const float* g, bool valid) {
    uint32_t sa = (uint32_t)__cvta_generic_to_shared(s);
    int sz = valid ? 16 : 0;
    asm volatile("cp.async.cg.shared.global [%0], [%1], 16, %2;\n"
                 :: "r"(sa), "l"(g), "r"(sz));
}
__device__ __forceinline__ void cp_commit() {
    asm volatile("cp.async.commit_group;\n");
}
template<int N>
__device__ __forceinline__ void cp_wait() {
    asm volatile("cp.async.wait_group %0;\n" :: "n"(N));
}

// ---------------------------------------------------------------------------
// Kernel 1: fused pools. blockIdx.z < 12: Q pool head z from x.
//           blockIdx.z >= 12: K+V dual pool head z-12 from x_ref.
// One warp per (token, bt, head).
// ---------------------------------------------------------------------------
__device__ __forceinline__ void ln_store(float v0, float v1,
                                         const float* __restrict__ gam,
                                         const float* __restrict__ bet,
                                         float* __restrict__ o, int c0, int c1) {
    float s = v0 + v1;
    #pragma unroll
    for (int off = 16; off > 0; off >>= 1) s += __shfl_xor_sync(0xffffffffu, s, off);
    float mu = s * (1.f / 64.f);
    float d0 = v0 - mu, d1 = v1 - mu;
    float vs = d0 * d0 + d1 * d1;
    #pragma unroll
    for (int off = 16; off > 0; off >>= 1) vs += __shfl_xor_sync(0xffffffffu, vs, off);
    float inv = rsqrtf(vs * (1.f / 64.f) + EPSLN);
    o[c0] = d0 * inv * gam[c0] + bet[c0];
    o[c1] = d1 * inv * gam[c1] + bet[c1];
}

__global__ void pool_all_kernel(const float* __restrict__ x,
                                const float* __restrict__ xr,
                                const float* __restrict__ cq,
                                const float* __restrict__ gq, const float* __restrict__ bq,
                                const float* __restrict__ ck,
                                const float* __restrict__ gk, const float* __restrict__ bk,
                                const float* __restrict__ cv,
                                const float* __restrict__ gv, const float* __restrict__ bv,
                                float* __restrict__ dq,
                                float* __restrict__ dk,
                                float* __restrict__ dv) {
    int n = blockIdx.x, bt = blockIdx.y, z = blockIdx.z;
    int lane = threadIdx.x, c0 = lane, c1 = lane + 32;
    size_t ob;
    if (z < NHEAD) {
        int h = z;
        float v0, v1;
        if (n == 0) {
            const float* p = x + ((size_t)bt * NTOK) * CC + h * HD;
            v0 = p[c0]; v1 = p[c1];
        } else {
            int io = (n - 1) / HP, jo = (n - 1) % HP;
            v0 = 0.f; v1 = 0.f;
            #pragma unroll
            for (int di = 0; di < 3; ++di) {
                int ii = 2 * io - 1 + di;
                if (ii < 0 || ii >= HH) continue;
                #pragma unroll
                for (int dj = 0; dj < 3; ++dj) {
                    int jj = 2 * jo - 1 + dj;
                    if (jj < 0 || jj >= WW) continue;
                    const float* p = x + ((size_t)bt * NTOK + 1 + ii * WW + jj) * CC + h * HD;
                    v0 += p[c0] * cq[(di * 3 + dj) * HD + c0];
                    v1 += p[c1] * cq[(di * 3 + dj) * HD + c1];
                }
            }
        }
        ob = ((size_t)bt * NQ + n) * CC + h * HD;
        ln_store(v0, v1, gq, bq, dq + ob, c0, c1);
    } else {
        int h = z - NHEAD;
        float k0, k1, v0, v1;
        if (n == 0) {
            const float* p = xr + ((size_t)bt * NTOK) * CC + h * HD;
            k0 = v0 = p[c0]; k1 = v1 = p[c1];
        } else {
            int io = (n - 1) / HP, jo = (n - 1) % HP;
            k0 = k1 = v0 = v1 = 0.f;
            #pragma unroll
            for (int di = 0; di < 3; ++di) {
                int ii = 2 * io - 1 + di;
                if (ii < 0 || ii >= HH) continue;
                #pragma unroll
                for (int dj = 0; dj < 3; ++dj) {
                    int jj = 2 * jo - 1 + dj;
                    if (jj < 0 || jj >= WW) continue;
                    const float* p = xr + ((size_t)bt * NTOK + 1 + ii * WW + jj) * CC + h * HD;
                    float a0 = p[c0], a1 = p[c1];
                    int wi = (di * 3 + dj) * HD;
                    k0 += a0 * ck[wi + c0]; k1 += a1 * ck[wi + c1];
                    v0 += a0 * cv[wi + c0]; v1 += a1 * cv[wi + c1];
                }
            }
        }
        ob = ((size_t)bt * NQ + n) * CC + h * HD;
        ln_store(k0, k1, gk, bk, dk + ob, c0, c1);
        ln_store(v0, v1, gv, bv, dv + ob, c0, c1);
    }
}

// ---------------------------------------------------------------------------
// Kernel 2: TF32 GEMM  C[M,768] = A[M,768] @ W[768,768]^T
// 64x128 tile, 8 warps (2x4, 32x32 each), cp.async double-buffered, k=32.
// MODE 0 (QKV fused over blockIdx.z): scatter to (b, head, l, d)
// MODE 1: row-major + bias
// ---------------------------------------------------------------------------
#define GROW 36                    // 32 k + 4 pad
#define ABUF (64*GROW)             // A floats per buffer
#define BBUF (128*GROW)            // B floats per buffer
#define GEMM_SMEM ((2*ABUF + 2*BBUF) * (int)sizeof(float))   // 55296 B

template<int MODE>
__global__ __launch_bounds__(256, 2)
void mma_gemm_kernel(const float* __restrict__ A0, const float* __restrict__ W0,
                     const float* __restrict__ C0,
                     const float* __restrict__ A1, const float* __restrict__ W1,
                     const float* __restrict__ C1,
                     const float* __restrict__ A2, const float* __restrict__ W2,
                     const float* __restrict__ C2,
                     const float* __restrict__ bias, int M) {
    extern __shared__ float sm[];
    float* As = sm;               // [2][64][GROW]
    float* Bs = sm + 2 * ABUF;    // [2][128][GROW]

    const float* A = (blockIdx.z == 0) ? A0 : (blockIdx.z == 1) ? A1 : A2;
    const float* W = (blockIdx.z == 0) ? W0 : (blockIdx.z == 1) ? W1 : W2;
    float* C = (float*)((blockIdx.z == 0) ? C0 : (blockIdx.z == 1) ? C1 : C2);

    const int tid  = threadIdx.x;
    const int lane = tid & 31;
    const int warp = tid >> 5;
    const int gid  = lane >> 2;
    const int tig  = lane & 3;
    const int wm   = warp >> 2;   // 0..1  (32-row slab)
    const int wn   = warp & 3;    // 0..3  (32-col slab)
    const int row0 = blockIdx.y * 64;
    const int col0 = blockIdx.x * 128;

    float acc[2][4][4];
    #pragma unroll
    for (int mt = 0; mt < 2; mt++)
        #pragma unroll
        for (int nt = 0; nt < 4; nt++)
            #pragma unroll
            for (int i = 0; i < 4; i++) acc[mt][nt][i] = 0.f;

    auto copy_chunk = [&](int chunk, int p) {
        int kc = chunk * 32;
        // A: 64 rows x 8 f4 = 512 f4 -> 2/thread
        #pragma unroll
        for (int i = 0; i < 2; i++) {
            int idx = i * 256 + tid;
            int r = idx >> 3, c4 = (idx & 7) * 4;
            int ar = row0 + r;
            bool av = ar < M;
            cp16(As + p * ABUF + r * GROW + c4,
                 A + (size_t)(av ? ar : 0) * 768 + kc + c4, av);
        }
        // B: 128 rows x 8 f4 = 1024 f4 -> 4/thread
        #pragma unroll
        for (int i = 0; i < 4; i++) {
            int idx = i * 256 + tid;
            int r = idx >> 3, c4 = (idx & 7) * 4;
            cp16(Bs + p * BBUF + r * GROW + c4,
                 W + (size_t)(col0 + r) * 768 + kc + c4, true);
        }
    };

    copy_chunk(0, 0);
    cp_commit();

    int p = 0;
    for (int chunk = 0; chunk < 24; chunk++) {
        if (chunk < 23) {
            copy_chunk(chunk + 1, p ^ 1);
            cp_commit();
            cp_wait<1>();
        } else {
            cp_wait<0>();
        }
        __syncthreads();

        const float* Ab = As + p * ABUF;
        const float* Bb = Bs + p * BBUF;
        #pragma unroll
        for (int ks = 0; ks < 4; ks++) {
            int k0 = ks * 8;
            uint32_t af[2][4], bf[4][2];
            #pragma unroll
            for (int mt = 0; mt < 2; mt++) {
                int m = wm * 32 + mt * 16 + gid;
                af[mt][0] = f2tf(Ab[(m    ) * GROW + k0 + tig]);
                af[mt][1] = f2tf(Ab[(m + 8) * GROW + k0 + tig]);
                af[mt][2] = f2tf(Ab[(m    ) * GROW + k0 + tig + 4]);
                af[mt][3] = f2tf(Ab[(m + 8) * GROW + k0 + tig + 4]);
            }
            #pragma unroll
            for (int nt = 0; nt < 4; nt++) {
                int n = wn * 32 + nt * 8 + gid;
                bf[nt][0] = f2tf(Bb[n * GROW + k0 + tig]);
                bf[nt][1] = f2tf(Bb[n * GROW + k0 + tig + 4]);
            }
            #pragma unroll
            for (int mt = 0; mt < 2; mt++)
                #pragma unroll
                for (int nt = 0; nt < 4; nt++)
                    mma_tf32(acc[mt][nt], af[mt], bf[nt]);
        }
        __syncthreads();
        p ^= 1;
    }

    // epilogue
    #pragma unroll
    for (int mt = 0; mt < 2; mt++) {
        #pragma unroll
        for (int rr = 0; rr < 2; rr++) {
            int m = row0 + wm * 32 + mt * 16 + gid + rr * 8;
            if (m >= M) continue;
            #pragma unroll
            for (int nt = 0; nt < 4; nt++) {
                int n = col0 + wn * 32 + nt * 8 + 2 * tig;
                float c0 = acc[mt][nt][rr * 2 + 0];
                float c1 = acc[mt][nt][rr * 2 + 1];
                if (MODE == 0) {
                    int b = m / LSEQ, l = m % LSEQ;
                    size_t o = (((size_t)(b * NHEAD + (n >> 6)) * LSEQ + l) << 6) + (n & 63);
                    *(float2*)(C + o) = make_float2(c0, c1);
                } else {
                    *(float2*)(C + (size_t)m * 768 + n) =
                        make_float2(c0 + bias[n], c1 + bias[n + 1]);
                }
            }
        }
    }
}

// ---------------------------------------------------------------------------
// Kernel 3: TF32 flash attention, cp.async double-buffered K/V, separate Ps.
// Block = (bh, 64-query tile), 4 warps, 16 rows/warp, 64-key tiles.
// ---------------------------------------------------------------------------
#define KPAD 68
#define VPAD 72
#define KTILE_F (64*KPAD)
#define VTILE_F (64*VPAD)

__global__ __launch_bounds__(128, 2)
void flash_mma_kernel(const float* __restrict__ Q, const float* __restrict__ Kp,
                      const float* __restrict__ Vp, float* __restrict__ O) {
    extern __shared__ float sm[];
    float* Ks = sm;                                   // [2][64][KPAD]
    float* Vs = sm + 2 * KTILE_F;                     // [2][64][VPAD]
    float* Pa = sm + 2 * KTILE_F + 2 * VTILE_F;       // [4][16][KPAD]

    const int tid  = threadIdx.x;
    const int lane = tid & 31;
    const int wid  = tid >> 5;
    const int gid  = lane >> 2;
    const int tig  = lane & 3;
    const int bh   = blockIdx.y;
    const int b    = bh / NHEAD;
    const int h    = bh % NHEAD;
    const int qrow0 = blockIdx.x * 64 + wid * 16;

    const float* Qb = Q + (size_t)bh * LSEQ * HD;
    const float* Kb = Kp + (size_t)bh * LSEQ * HD;
    const float* Vb = Vp + (size_t)bh * LSEQ * HD;

    uint32_t qf[8][4];
    {
        int rl = min(qrow0 + gid, LSEQ - 1);
        int rh = min(qrow0 + gid + 8, LSEQ - 1);
        #pragma unroll
        for (int ks = 0; ks < 8; ks++) {
            qf[ks][0] = f2tf(0.125f * Qb[(size_t)rl * HD + ks * 8 + tig]);
            qf[ks][1] = f2tf(0.125f * Qb[(size_t)rh * HD + ks * 8 + tig]);
            qf[ks][2] = f2tf(0.125f * Qb[(size_t)rl * HD + ks * 8 + tig + 4]);
            qf[ks][3] = f2tf(0.125f * Qb[(size_t)rh * HD + ks * 8 + tig + 4]);
        }
    }

    float off[8][4];
    #pragma unroll
    for (int nt = 0; nt < 8; nt++)
        #pragma unroll
        for (int i = 0; i < 4; i++) off[nt][i] = 0.f;
    float m0 = -1e30f, m1 = -1e30f, l0 = 0.f, l1 = 0.f;

    float* Ps = Pa + wid * 16 * KPAD;

    auto copy_tile = [&](int t, int p) {
        int kt0 = t * 64;
        #pragma unroll
        for (int i = 0; i < 8; i++) {
            int idx = i * 128 + tid;
            int r = idx >> 4, c4 = (idx & 15) * 4;
            bool v = kt0 + r < LSEQ;
            int key = v ? (kt0 + r) : 0;
            cp16(Ks + p * KTILE_F + r * KPAD + c4, Kb + (size_t)key * HD + c4, v);
            cp16(Vs + p * VTILE_F + r * VPAD + c4, Vb + (size_t)key * HD + c4, v);
        }
    };

    const int NT = (LSEQ + 63) / 64;   // 25
    copy_tile(0, 0);
    cp_commit();

    int p = 0;
    for (int t = 0; t < NT; t++) {
        if (t < NT - 1) {
            copy_tile(t + 1, p ^ 1);
            cp_commit();
            cp_wait<1>();
        } else {
            cp_wait<0>();
        }
        __syncthreads();

        const float* Kt = Ks + p * KTILE_F;
        const float* Vt = Vs + p * VTILE_F;
        int kt0 = t * 64;

        float sf[8][4];
        #pragma unroll
        for (int nt = 0; nt < 8; nt++)
            #pragma unroll
            for (int i = 0; i < 4; i++) sf[nt][i] = 0.f;

        #pragma unroll
        for (int nt = 0; nt < 8; nt++) {
            const float* krow = Kt + (nt * 8 + gid) * KPAD;
            #pragma unroll
            for (int ks = 0; ks < 8; ks++) {
                uint32_t bf[2];
                bf[0] = f2tf(krow[ks * 8 + tig]);
                bf[1] = f2tf(krow[ks * 8 + tig + 4]);
                mma_tf32(sf[nt], qf[ks], bf);
            }
        }

        if (kt0 + 64 > LSEQ) {
            #pragma unroll
            for (int nt = 0; nt < 8; nt++) {
                int c = kt0 + nt * 8 + 2 * tig;
                if (c >= LSEQ)     { sf[nt][0] = -1e30f; sf[nt][2] = -1e30f; }
                if (c + 1 >= LSEQ) { sf[nt][1] = -1e30f; sf[nt][3] = -1e30f; }
            }
        }

        float rmax0 = -1e30f, rmax1 = -1e30f;
        #pragma unroll
        for (int nt = 0; nt < 8; nt++) {
            rmax0 = fmaxf(rmax0, fmaxf(sf[nt][0], sf[nt][1]));
            rmax1 = fmaxf(rmax1, fmaxf(sf[nt][2], sf[nt][3]));
        }
        #pragma unroll
        for (int o = 1; o <= 2; o <<= 1) {
            rmax0 = fmaxf(rmax0, __shfl_xor_sync(0xffffffffu, rmax0, o));
            rmax1 = fmaxf(rmax1, __shfl_xor_sync(0xffffffffu, rmax1, o));
        }
        float mn0 = fmaxf(m0, rmax0), mn1 = fmaxf(m1, rmax1);
        float sc0 = __expf(m0 - mn0), sc1 = __expf(m1 - mn1);
        m0 = mn0; m1 = mn1;

        float rs0 = 0.f, rs1 = 0.f;
        #pragma unroll
        for (int nt = 0; nt < 8; nt++) {
            float p0 = __expf(sf[nt][0] - m0);
            float p1 = __expf(sf[nt][1] - m0);
            float p2 = __expf(sf[nt][2] - m1);
            float p3 = __expf(sf[nt][3] - m1);
            rs0 += p0 + p1; rs1 += p2 + p3;
            *(float2*)(Ps + gid * KPAD + nt * 8 + 2 * tig) =
                make_float2(f2tff(p0), f2tff(p1));
            *(float2*)(Ps + (gid + 8) * KPAD + nt * 8 + 2 * tig) =
                make_float2(f2tff(p2), f2tff(p3));
        }
        #pragma unroll
        for (int o = 1; o <= 2; o <<= 1) {
            rs0 += __shfl_xor_sync(0xffffffffu, rs0, o);
            rs1 += __shfl_xor_sync(0xffffffffu, rs1, o);
        }
        l0 = l0 * sc0 + rs0;
        l1 = l1 * sc1 + rs1;
        #pragma unroll
        for (int nt = 0; nt < 8; nt++) {
            off[nt][0] *= sc0; off[nt][1] *= sc0;
            off[nt][2] *= sc1; off[nt][3] *= sc1;
        }
        __syncwarp();

        #pragma unroll
        for (int ks = 0; ks < 8; ks++) {
            uint32_t af[4];
            af[0] = __float_as_uint(Ps[gid * KPAD + ks * 8 + tig]);
            af[1] = __float_as_uint(Ps[(gid + 8) * KPAD + ks * 8 + tig]);
            af[2] = __float_as_uint(Ps[gid * KPAD + ks * 8 + tig + 4]);
            af[3] = __float_as_uint(Ps[(gid + 8) * KPAD + ks * 8 + tig + 4]);
            #pragma unroll
            for (int nt = 0; nt < 8; nt++) {
                uint32_t bf[2];
                bf[0] = f2tf(Vt[(ks * 8 + tig) * VPAD + nt * 8 + gid]);
                bf[1] = f2tf(Vt[(ks * 8 + tig + 4) * VPAD + nt * 8 + gid]);
                mma_tf32(off[nt], af, bf);
            }
        }
        __syncthreads();
        p ^= 1;
    }

    float inv0 = 1.f / l0, inv1 = 1.f / l1;
    #pragma unroll
    for (int rr = 0; rr < 2; rr++) {
        int row = qrow0 + gid + rr * 8;
        if (row >= LSEQ) continue;
        float inv = rr ? inv1 : inv0;
        float resid = (row != 0) ? 1.f : 0.f;
        float* op = O + ((size_t)(b * LSEQ + row)) * CC + h * HD;
        #pragma unroll
        for (int nt = 0; nt < 8; nt++) {
            int c = nt * 8 + 2 * tig;
            float2 qv = *(const float2*)(Qb + (size_t)row * HD + c);
            float v0 = off[nt][rr * 2 + 0] * inv + resid * qv.x;
            float v1 = off[nt][rr * 2 + 1] * inv + resid * qv.y;
            *(float2*)(op + c) = make_float2(v0, v1);
        }
    }
}

// ---------------------------------------------------------------------------
extern "C" void kernel_launch(void* const* d_in, const int* in_sizes, int n_in,
                              void* d_out, int out_size) {
    const float* x  = (const float*)d_in[0];
    const float* xr = (const float*)d_in[1];
    const float* wq = (const float*)d_in[2];
    const float* wk = (const float*)d_in[3];
    const float* wv = (const float*)d_in[4];
    const float* wp = (const float*)d_in[5];
    const float* bp = (const float*)d_in[6];
    const float* cq = (const float*)d_in[7];
    const float* ck = (const float*)d_in[8];
    const float* cv = (const float*)d_in[9];
    const float* gq = (const float*)d_in[10];
    const float* bq = (const float*)d_in[11];
    const float* gk = (const float*)d_in[12];
    const float* bk = (const float*)d_in[13];
    const float* gv = (const float*)d_in[14];
    const float* bv = (const float*)d_in[15];
    float* out = (float*)d_out;

    float *pq, *pk, *pv, *qd, *kd, *vd, *ao;
    cudaGetSymbolAddress((void**)&pq, g_poolq);
    cudaGetSymbolAddress((void**)&pk, g_poolk);
    cudaGetSymbolAddress((void**)&pv, g_poolv);
    cudaGetSymbolAddress((void**)&qd, g_q);
    cudaGetSymbolAddress((void**)&kd, g_k);
    cudaGetSymbolAddress((void**)&vd, g_v);
    cudaGetSymbolAddress((void**)&ao, g_ao);

    const int flash_smem = (2 * KTILE_F + 2 * VTILE_F + 4 * 16 * KPAD) * (int)sizeof(float);
    cudaFuncSetAttribute(mma_gemm_kernel<0>, cudaFuncAttributeMaxDynamicSharedMemorySize, GEMM_SMEM);
    cudaFuncSetAttribute(mma_gemm_kernel<1>, cudaFuncAttributeMaxDynamicSharedMemorySize, GEMM_SMEM);
    cudaFuncSetAttribute(flash_mma_kernel,   cudaFuncAttributeMaxDynamicSharedMemorySize, flash_smem);

    dim3 pg(NQ, BT, 2 * NHEAD);
    pool_all_kernel<<<pg, 32>>>(x, xr, cq, gq, bq, ck, gk, bk, cv, gv, bv, pq, pk, pv);

    dim3 gq3(CC / 128, (MR + 63) / 64, 3);
    mma_gemm_kernel<0><<<gq3, 256, GEMM_SMEM>>>(pq, wq, qd, pk, wk, kd, pv, wv, vd,
                                                nullptr, MR);

    dim3 fg((LSEQ + 63) / 64, BATCH * NHEAD);
    flash_mma_kernel<<<fg, 128, flash_smem>>>(qd, kd, vd, ao);

    dim3 gp(CC / 128, (MR + 63) / 64, 1);
    mma_gemm_kernel<1><<<gp, 256, GEMM_SMEM>>>(ao, wp, out, nullptr, nullptr, nullptr,
                                               nullptr, nullptr, nullptr, bp, MR);
}

// round 6
// speedup vs baseline: 5.1467x; 1.0551x over previous
#include <cuda_runtime.h>
#include <math.h>
#include <stdint.h>

// Problem constants (fixed by reference setup_inputs)
#define BATCH 2
#define TT    8
#define HH    28
#define WW    28
#define CC    768
#define NHEAD 12
#define HD    64
#define NTOK  785        // 1 + 28*28
#define HP    14
#define NQ    197        // 1 + 14*14
#define BT    (BATCH*TT) // 16
#define LSEQ  (TT*NQ)    // 1576
#define EPSLN 1e-5f
#define MR    (BT*NQ)    // 3152 rows for GEMMs

// Scratch (static device globals; no runtime allocation allowed)
__device__ float g_poolq[BT*NQ*CC];
__device__ float g_poolk[BT*NQ*CC];
__device__ float g_poolv[BT*NQ*CC];
__device__ float g_q [BT*NQ*CC];  // (b, h, l, d) raw fp32 (residual)
__device__ float g_qs[BT*NQ*CC];  // (b, h, l, d) 0.125*q, tf32-rounded
__device__ float g_k [BT*NQ*CC];  // tf32-rounded
__device__ float g_v [BT*NQ*CC];  // tf32-rounded
__device__ float g_ao[BT*NQ*CC];  // (b*l, C), tf32-rounded
__device__ float g_wq[CC*CC];     // tf32-rounded weights
__device__ float g_wk[CC*CC];
__device__ float g_wv[CC*CC];
__device__ float g_wp[CC*CC];

// ---------------------------------------------------------------------------
// helpers
// ---------------------------------------------------------------------------
__device__ __forceinline__ uint32_t f2tf(float x) {
    uint32_t r;
    asm("cvt.rna.tf32.f32 %0, %1;" : "=r"(r) : "f"(x));
    return r;
}
__device__ __forceinline__ float f2tff(float x) {
    return __uint_as_float(f2tf(x));
}
__device__ __forceinline__ void mma_tf32(float* d, const uint32_t* a, const uint32_t* b) {
    asm volatile(
        "mma.sync.aligned.m16n8k8.row.col.f32.tf32.tf32.f32 "
        "{%0,%1,%2,%3}, {%4,%5,%6,%7}, {%8,%9}, {%0,%1,%2,%3};\n"
        : "+f"(d[0]), "+f"(d[1]), "+f"(d[2]), "+f"(d[3])
        : "r"(a[0]), "r"(a[1]), "r"(a[2]), "r"(a[3]), "r"(b[0]), "r"(b[1]));
}
__device__ __forceinline__ void cp16(float* s, const float* g, bool valid) {
    uint32_t sa = (uint32_t)__cvta_generic_to_shared(s);
    int sz = valid ? 16 : 0;
    asm volatile("cp.async.cg.shared.global [%0], [%1], 16, %2;\n"
                 :: "r"(sa), "l"(g), "r"(sz));
}
__device__ __forceinline__ void cp_commit() {
    asm volatile("cp.async.commit_group;\n");
}
template<int N>
__device__ __forceinline__ void cp_wait() {
    asm volatile("cp.async.wait_group %0;\n" :: "n"(N));
}

// ---------------------------------------------------------------------------
// Kernel 0: pre-round weights to tf32 (once per launch; HBM-bound, tiny)
// ---------------------------------------------------------------------------
__global__ void round_w_kernel(const float* __restrict__ w0, const float* __restrict__ w1,
                               const float* __restrict__ w2, const float* __restrict__ w3,
                               float* __restrict__ o0, float* __restrict__ o1,
                               float* __restrict__ o2, float* __restrict__ o3) {
    int z = blockIdx.y;
    const float* s = (z == 0) ? w0 : (z == 1) ? w1 : (z == 2) ? w2 : w3;
    float* d = (z == 0) ? o0 : (z == 1) ? o1 : (z == 2) ? o2 : o3;
    int idx = blockIdx.x * 256 + threadIdx.x;    // float4 index; CC*CC/4 = 147456
    float4 v = ((const float4*)s)[idx];
    ((float4*)d)[idx] = make_float4(f2tff(v.x), f2tff(v.y), f2tff(v.z), f2tff(v.w));
}

// ---------------------------------------------------------------------------
// Kernel 1: fused pools (outputs tf32-rounded; they only feed the GEMM).
// blockIdx.z < 12: Q pool head z; z >= 12: K+V dual pool head z-12.
// ---------------------------------------------------------------------------
__device__ __forceinline__ void ln_store(float v0, float v1,
                                         const float* __restrict__ gam,
                                         const float* __restrict__ bet,
                                         float* __restrict__ o, int c0, int c1) {
    float s = v0 + v1;
    #pragma unroll
    for (int off = 16; off > 0; off >>= 1) s += __shfl_xor_sync(0xffffffffu, s, off);
    float mu = s * (1.f / 64.f);
    float d0 = v0 - mu, d1 = v1 - mu;
    float vs = d0 * d0 + d1 * d1;
    #pragma unroll
    for (int off = 16; off > 0; off >>= 1) vs += __shfl_xor_sync(0xffffffffu, vs, off);
    float inv = rsqrtf(vs * (1.f / 64.f) + EPSLN);
    o[c0] = f2tff(d0 * inv * gam[c0] + bet[c0]);
    o[c1] = f2tff(d1 * inv * gam[c1] + bet[c1]);
}

__global__ void pool_all_kernel(const float* __restrict__ x,
                                const float* __restrict__ xr,
                                const float* __restrict__ cq,
                                const float* __restrict__ gq, const float* __restrict__ bq,
                                const float* __restrict__ ck,
                                const float* __restrict__ gk, const float* __restrict__ bk,
                                const float* __restrict__ cv,
                                const float* __restrict__ gv, const float* __restrict__ bv,
                                float* __restrict__ dq,
                                float* __restrict__ dk,
                                float* __restrict__ dv) {
    int n = blockIdx.x, bt = blockIdx.y, z = blockIdx.z;
    int lane = threadIdx.x, c0 = lane, c1 = lane + 32;
    size_t ob;
    if (z < NHEAD) {
        int h = z;
        float v0, v1;
        if (n == 0) {
            const float* p = x + ((size_t)bt * NTOK) * CC + h * HD;
            v0 = p[c0]; v1 = p[c1];
        } else {
            int io = (n - 1) / HP, jo = (n - 1) % HP;
            v0 = 0.f; v1 = 0.f;
            #pragma unroll
            for (int di = 0; di < 3; ++di) {
                int ii = 2 * io - 1 + di;
                if (ii < 0 || ii >= HH) continue;
                #pragma unroll
                for (int dj = 0; dj < 3; ++dj) {
                    int jj = 2 * jo - 1 + dj;
                    if (jj < 0 || jj >= WW) continue;
                    const float* p = x + ((size_t)bt * NTOK + 1 + ii * WW + jj) * CC + h * HD;
                    v0 += p[c0] * cq[(di * 3 + dj) * HD + c0];
                    v1 += p[c1] * cq[(di * 3 + dj) * HD + c1];
                }
            }
        }
        ob = ((size_t)bt * NQ + n) * CC + h * HD;
        ln_store(v0, v1, gq, bq, dq + ob, c0, c1);
    } else {
        int h = z - NHEAD;
        float k0, k1, v0, v1;
        if (n == 0) {
            const float* p = xr + ((size_t)bt * NTOK) * CC + h * HD;
            k0 = v0 = p[c0]; k1 = v1 = p[c1];
        } else {
            int io = (n - 1) / HP, jo = (n - 1) % HP;
            k0 = k1 = v0 = v1 = 0.f;
            #pragma unroll
            for (int di = 0; di < 3; ++di) {
                int ii = 2 * io - 1 + di;
                if (ii < 0 || ii >= HH) continue;
                #pragma unroll
                for (int dj = 0; dj < 3; ++dj) {
                    int jj = 2 * jo - 1 + dj;
                    if (jj < 0 || jj >= WW) continue;
                    const float* p = xr + ((size_t)bt * NTOK + 1 + ii * WW + jj) * CC + h * HD;
                    float a0 = p[c0], a1 = p[c1];
                    int wi = (di * 3 + dj) * HD;
                    k0 += a0 * ck[wi + c0]; k1 += a1 * ck[wi + c1];
                    v0 += a0 * cv[wi + c0]; v1 += a1 * cv[wi + c1];
                }
            }
        }
        ob = ((size_t)bt * NQ + n) * CC + h * HD;
        ln_store(k0, k1, gk, bk, dk + ob, c0, c1);
        ln_store(v0, v1, gv, bv, dv + ob, c0, c1);
    }
}

// ---------------------------------------------------------------------------
// Kernel 2: TF32 GEMM  C[M,768] = A[M,768] @ W[768,768]^T
// Inputs are pre-tf32-rounded: fragment loads are plain LDS (no cvt).
// 64x128 tile, 8 warps (2x4, 32x32 each), cp.async double-buffered, k=32.
// MODE 0 (fused QKV over blockIdx.z): z=0 stores raw q + scaled/rounded qs;
//        z=1,2 store tf32-rounded k/v. All in (b, head, l, d).
// MODE 1: row-major + bias, fp32 (final output).
// ---------------------------------------------------------------------------
#define GROW 36                    // 32 k + 4 pad
#define ABUF (64*GROW)
#define BBUF (128*GROW)
#define GEMM_SMEM ((2*ABUF + 2*BBUF) * (int)sizeof(float))   // 55296 B

template<int MODE>
__global__ __launch_bounds__(256, 2)
void mma_gemm_kernel(const float* __restrict__ A0, const float* __restrict__ W0,
                     const float* __restrict__ C0,
                     const float* __restrict__ A1, const float* __restrict__ W1,
                     const float* __restrict__ C1,
                     const float* __restrict__ A2, const float* __restrict__ W2,
                     const float* __restrict__ C2,
                     const float* __restrict__ Cs,   // qs (z==0 only)
                     const float* __restrict__ bias, int M) {
    extern __shared__ float sm[];
    float* As = sm;               // [2][64][GROW]
    float* Bs = sm + 2 * ABUF;    // [2][128][GROW]

    const float* A = (blockIdx.z == 0) ? A0 : (blockIdx.z == 1) ? A1 : A2;
    const float* W = (blockIdx.z == 0) ? W0 : (blockIdx.z == 1) ? W1 : W2;
    float* C  = (float*)((blockIdx.z == 0) ? C0 : (blockIdx.z == 1) ? C1 : C2);
    float* Cq = (float*)Cs;

    const int tid  = threadIdx.x;
    const int lane = tid & 31;
    const int warp = tid >> 5;
    const int gid  = lane >> 2;
    const int tig  = lane & 3;
    const int wm   = warp >> 2;
    const int wn   = warp & 3;
    const int row0 = blockIdx.y * 64;
    const int col0 = blockIdx.x * 128;

    float acc[2][4][4];
    #pragma unroll
    for (int mt = 0; mt < 2; mt++)
        #pragma unroll
        for (int nt = 0; nt < 4; nt++)
            #pragma unroll
            for (int i = 0; i < 4; i++) acc[mt][nt][i] = 0.f;

    auto copy_chunk = [&](int chunk, int p) {
        int kc = chunk * 32;
        #pragma unroll
        for (int i = 0; i < 2; i++) {
            int idx = i * 256 + tid;
            int r = idx >> 3, c4 = (idx & 7) * 4;
            int ar = row0 + r;
            bool av = ar < M;
            cp16(As + p * ABUF + r * GROW + c4,
                 A + (size_t)(av ? ar : 0) * 768 + kc + c4, av);
        }
        #pragma unroll
        for (int i = 0; i < 4; i++) {
            int idx = i * 256 + tid;
            int r = idx >> 3, c4 = (idx & 7) * 4;
            cp16(Bs + p * BBUF + r * GROW + c4,
                 W + (size_t)(col0 + r) * 768 + kc + c4, true);
        }
    };

    copy_chunk(0, 0);
    cp_commit();

    int p = 0;
    for (int chunk = 0; chunk < 24; chunk++) {
        if (chunk < 23) {
            copy_chunk(chunk + 1, p ^ 1);
            cp_commit();
            cp_wait<1>();
        } else {
            cp_wait<0>();
        }
        __syncthreads();

        const float* Ab = As + p * ABUF;
        const float* Bb = Bs + p * BBUF;
        #pragma unroll
        for (int ks = 0; ks < 4; ks++) {
            int k0 = ks * 8;
            uint32_t af[2][4], bf[4][2];
            #pragma unroll
            for (int mt = 0; mt < 2; mt++) {
                int m = wm * 32 + mt * 16 + gid;
                af[mt][0] = __float_as_uint(Ab[(m    ) * GROW + k0 + tig]);
                af[mt][1] = __float_as_uint(Ab[(m + 8) * GROW + k0 + tig]);
                af[mt][2] = __float_as_uint(Ab[(m    ) * GROW + k0 + tig + 4]);
                af[mt][3] = __float_as_uint(Ab[(m + 8) * GROW + k0 + tig + 4]);
            }
            #pragma unroll
            for (int nt = 0; nt < 4; nt++) {
                int n = wn * 32 + nt * 8 + gid;
                bf[nt][0] = __float_as_uint(Bb[n * GROW + k0 + tig]);
                bf[nt][1] = __float_as_uint(Bb[n * GROW + k0 + tig + 4]);
            }
            #pragma unroll
            for (int mt = 0; mt < 2; mt++)
                #pragma unroll
                for (int nt = 0; nt < 4; nt++)
                    mma_tf32(acc[mt][nt], af[mt], bf[nt]);
        }
        __syncthreads();
        p ^= 1;
    }

    // epilogue
    #pragma unroll
    for (int mt = 0; mt < 2; mt++) {
        #pragma unroll
        for (int rr = 0; rr < 2; rr++) {
            int m = row0 + wm * 32 + mt * 16 + gid + rr * 8;
            if (m >= M) continue;
            #pragma unroll
            for (int nt = 0; nt < 4; nt++) {
                int n = col0 + wn * 32 + nt * 8 + 2 * tig;
                float c0 = acc[mt][nt][rr * 2 + 0];
                float c1 = acc[mt][nt][rr * 2 + 1];
                if (MODE == 0) {
                    int b = m / LSEQ, l = m % LSEQ;
                    size_t o = (((size_t)(b * NHEAD + (n >> 6)) * LSEQ + l) << 6) + (n & 63);
                    if (blockIdx.z == 0) {
                        *(float2*)(C + o)  = make_float2(c0, c1);
                        *(float2*)(Cq + o) = make_float2(f2tff(0.125f * c0),
                                                         f2tff(0.125f * c1));
                    } else {
                        *(float2*)(C + o) = make_float2(f2tff(c0), f2tff(c1));
                    }
                } else {
                    *(float2*)(C + (size_t)m * 768 + n) =
                        make_float2(c0 + bias[n], c1 + bias[n + 1]);
                }
            }
        }
    }
}

// ---------------------------------------------------------------------------
// Kernel 3: TF32 flash attention. All inputs pre-rounded (no cvt on Q/K/V
// fragments; only P gets cvt). cp.async double-buffered K/V, separate Ps.
// ---------------------------------------------------------------------------
#define KPAD 68
#define VPAD 72
#define KTILE_F (64*KPAD)
#define VTILE_F (64*VPAD)

__global__ __launch_bounds__(128, 2)
void flash_mma_kernel(const float* __restrict__ Qs, const float* __restrict__ Qraw,
                      const float* __restrict__ Kp, const float* __restrict__ Vp,
                      float* __restrict__ O) {
    extern __shared__ float sm[];
    float* Ks = sm;
    float* Vs = sm + 2 * KTILE_F;
    float* Pa = sm + 2 * KTILE_F + 2 * VTILE_F;

    const int tid  = threadIdx.x;
    const int lane = tid & 31;
    const int wid  = tid >> 5;
    const int gid  = lane >> 2;
    const int tig  = lane & 3;
    const int bh   = blockIdx.y;
    const int b    = bh / NHEAD;
    const int h    = bh % NHEAD;
    const int qrow0 = blockIdx.x * 64 + wid * 16;

    const float* Qsb = Qs + (size_t)bh * LSEQ * HD;
    const float* Qb  = Qraw + (size_t)bh * LSEQ * HD;
    const float* Kb  = Kp + (size_t)bh * LSEQ * HD;
    const float* Vb  = Vp + (size_t)bh * LSEQ * HD;

    uint32_t qf[8][4];
    {
        int rl = min(qrow0 + gid, LSEQ - 1);
        int rh = min(qrow0 + gid + 8, LSEQ - 1);
        #pragma unroll
        for (int ks = 0; ks < 8; ks++) {
            qf[ks][0] = __float_as_uint(Qsb[(size_t)rl * HD + ks * 8 + tig]);
            qf[ks][1] = __float_as_uint(Qsb[(size_t)rh * HD + ks * 8 + tig]);
            qf[ks][2] = __float_as_uint(Qsb[(size_t)rl * HD + ks * 8 + tig + 4]);
            qf[ks][3] = __float_as_uint(Qsb[(size_t)rh * HD + ks * 8 + tig + 4]);
        }
    }

    float off[8][4];
    #pragma unroll
    for (int nt = 0; nt < 8; nt++)
        #pragma unroll
        for (int i = 0; i < 4; i++) off[nt][i] = 0.f;
    float m0 = -1e30f, m1 = -1e30f, l0 = 0.f, l1 = 0.f;

    float* Ps = Pa + wid * 16 * KPAD;

    auto copy_tile = [&](int t, int p) {
        int kt0 = t * 64;
        #pragma unroll
        for (int i = 0; i < 8; i++) {
            int idx = i * 128 + tid;
            int r = idx >> 4, c4 = (idx & 15) * 4;
            bool v = kt0 + r < LSEQ;
            int key = v ? (kt0 + r) : 0;
            cp16(Ks + p * KTILE_F + r * KPAD + c4, Kb + (size_t)key * HD + c4, v);
            cp16(Vs + p * VTILE_F + r * VPAD + c4, Vb + (size_t)key * HD + c4, v);
        }
    };

    const int NT = (LSEQ + 63) / 64;
    copy_tile(0, 0);
    cp_commit();

    int p = 0;
    for (int t = 0; t < NT; t++) {
        if (t < NT - 1) {
            copy_tile(t + 1, p ^ 1);
            cp_commit();
            cp_wait<1>();
        } else {
            cp_wait<0>();
        }
        __syncthreads();

        const float* Kt = Ks + p * KTILE_F;
        const float* Vt = Vs + p * VTILE_F;
        int kt0 = t * 64;

        float sf[8][4];
        #pragma unroll
        for (int nt = 0; nt < 8; nt++)
            #pragma unroll
            for (int i = 0; i < 4; i++) sf[nt][i] = 0.f;

        #pragma unroll
        for (int nt = 0; nt < 8; nt++) {
            const float* krow = Kt + (nt * 8 + gid) * KPAD;
            #pragma unroll
            for (int ks = 0; ks < 8; ks++) {
                uint32_t bf[2];
                bf[0] = __float_as_uint(krow[ks * 8 + tig]);
                bf[1] = __float_as_uint(krow[ks * 8 + tig + 4]);
                mma_tf32(sf[nt], qf[ks], bf);
            }
        }

        if (kt0 + 64 > LSEQ) {
            #pragma unroll
            for (int nt = 0; nt < 8; nt++) {
                int c = kt0 + nt * 8 + 2 * tig;
                if (c >= LSEQ)     { sf[nt][0] = -1e30f; sf[nt][2] = -1e30f; }
                if (c + 1 >= LSEQ) { sf[nt][1] = -1e30f; sf[nt][3] = -1e30f; }
            }
        }

        float rmax0 = -1e30f, rmax1 = -1e30f;
        #pragma unroll
        for (int nt = 0; nt < 8; nt++) {
            rmax0 = fmaxf(rmax0, fmaxf(sf[nt][0], sf[nt][1]));
            rmax1 = fmaxf(rmax1, fmaxf(sf[nt][2], sf[nt][3]));
        }
        #pragma unroll
        for (int o = 1; o <= 2; o <<= 1) {
            rmax0 = fmaxf(rmax0, __shfl_xor_sync(0xffffffffu, rmax0, o));
            rmax1 = fmaxf(rmax1, __shfl_xor_sync(0xffffffffu, rmax1, o));
        }
        float mn0 = fmaxf(m0, rmax0), mn1 = fmaxf(m1, rmax1);
        float sc0 = __expf(m0 - mn0), sc1 = __expf(m1 - mn1);
        m0 = mn0; m1 = mn1;

        float rs0 = 0.f, rs1 = 0.f;
        #pragma unroll
        for (int nt = 0; nt < 8; nt++) {
            float p0 = __expf(sf[nt][0] - m0);
            float p1 = __expf(sf[nt][1] - m0);
            float p2 = __expf(sf[nt][2] - m1);
            float p3 = __expf(sf[nt][3] - m1);
            rs0 += p0 + p1; rs1 += p2 + p3;
            *(float2*)(Ps + gid * KPAD + nt * 8 + 2 * tig) =
                make_float2(f2tff(p0), f2tff(p1));
            *(float2*)(Ps + (gid + 8) * KPAD + nt * 8 + 2 * tig) =
                make_float2(f2tff(p2), f2tff(p3));
        }
        #pragma unroll
        for (int o = 1; o <= 2; o <<= 1) {
            rs0 += __shfl_xor_sync(0xffffffffu, rs0, o);
            rs1 += __shfl_xor_sync(0xffffffffu, rs1, o);
        }
        l0 = l0 * sc0 + rs0;
        l1 = l1 * sc1 + rs1;
        #pragma unroll
        for (int nt = 0; nt < 8; nt++) {
            off[nt][0] *= sc0; off[nt][1] *= sc0;
            off[nt][2] *= sc1; off[nt][3] *= sc1;
        }
        __syncwarp();

        #pragma unroll
        for (int ks = 0; ks < 8; ks++) {
            uint32_t af[4];
            af[0] = __float_as_uint(Ps[gid * KPAD + ks * 8 + tig]);
            af[1] = __float_as_uint(Ps[(gid + 8) * KPAD + ks * 8 + tig]);
            af[2] = __float_as_uint(Ps[gid * KPAD + ks * 8 + tig + 4]);
            af[3] = __float_as_uint(Ps[(gid + 8) * KPAD + ks * 8 + tig + 4]);
            #pragma unroll
            for (int nt = 0; nt < 8; nt++) {
                uint32_t bf[2];
                bf[0] = __float_as_uint(Vt[(ks * 8 + tig) * VPAD + nt * 8 + gid]);
                bf[1] = __float_as_uint(Vt[(ks * 8 + tig + 4) * VPAD + nt * 8 + gid]);
                mma_tf32(off[nt], af, bf);
            }
        }
        __syncthreads();
        p ^= 1;
    }

    float inv0 = 1.f / l0, inv1 = 1.f / l1;
    #pragma unroll
    for (int rr = 0; rr < 2; rr++) {
        int row = qrow0 + gid + rr * 8;
        if (row >= LSEQ) continue;
        float inv = rr ? inv1 : inv0;
        float resid = (row != 0) ? 1.f : 0.f;
        float* op = O + ((size_t)(b * LSEQ + row)) * CC + h * HD;
        #pragma unroll
        for (int nt = 0; nt < 8; nt++) {
            int c = nt * 8 + 2 * tig;
            float2 qv = *(const float2*)(Qb + (size_t)row * HD + c);
            float v0 = f2tff(off[nt][rr * 2 + 0] * inv + resid * qv.x);
            float v1 = f2tff(off[nt][rr * 2 + 1] * inv + resid * qv.y);
            *(float2*)(op + c) = make_float2(v0, v1);
        }
    }
}

// ---------------------------------------------------------------------------
extern "C" void kernel_launch(void* const* d_in, const int* in_sizes, int n_in,
                              void* d_out, int out_size) {
    const float* x  = (const float*)d_in[0];
    const float* xr = (const float*)d_in[1];
    const float* wq = (const float*)d_in[2];
    const float* wk = (const float*)d_in[3];
    const float* wv = (const float*)d_in[4];
    const float* wp = (const float*)d_in[5];
    const float* bp = (const float*)d_in[6];
    const float* cq = (const float*)d_in[7];
    const float* ck = (const float*)d_in[8];
    const float* cv = (const float*)d_in[9];
    const float* gq = (const float*)d_in[10];
    const float* bq = (const float*)d_in[11];
    const float* gk = (const float*)d_in[12];
    const float* bk = (const float*)d_in[13];
    const float* gv = (const float*)d_in[14];
    const float* bv = (const float*)d_in[15];
    float* out = (float*)d_out;

    float *pq, *pk, *pv, *qd, *qs, *kd, *vd, *ao, *rwq, *rwk, *rwv, *rwp;
    cudaGetSymbolAddress((void**)&pq, g_poolq);
    cudaGetSymbolAddress((void**)&pk, g_poolk);
    cudaGetSymbolAddress((void**)&pv, g_poolv);
    cudaGetSymbolAddress((void**)&qd, g_q);
    cudaGetSymbolAddress((void**)&qs, g_qs);
    cudaGetSymbolAddress((void**)&kd, g_k);
    cudaGetSymbolAddress((void**)&vd, g_v);
    cudaGetSymbolAddress((void**)&ao, g_ao);
    cudaGetSymbolAddress((void**)&rwq, g_wq);
    cudaGetSymbolAddress((void**)&rwk, g_wk);
    cudaGetSymbolAddress((void**)&rwv, g_wv);
    cudaGetSymbolAddress((void**)&rwp, g_wp);

    const int flash_smem = (2 * KTILE_F + 2 * VTILE_F + 4 * 16 * KPAD) * (int)sizeof(float);
    cudaFuncSetAttribute(mma_gemm_kernel<0>, cudaFuncAttributeMaxDynamicSharedMemorySize, GEMM_SMEM);
    cudaFuncSetAttribute(mma_gemm_kernel<1>, cudaFuncAttributeMaxDynamicSharedMemorySize, GEMM_SMEM);
    cudaFuncSetAttribute(flash_mma_kernel,   cudaFuncAttributeMaxDynamicSharedMemorySize, flash_smem);

    dim3 wg(CC * CC / 4 / 256, 4);
    round_w_kernel<<<wg, 256>>>(wq, wk, wv, wp, rwq, rwk, rwv, rwp);

    dim3 pg(NQ, BT, 2 * NHEAD);
    pool_all_kernel<<<pg, 32>>>(x, xr, cq, gq, bq, ck, gk, bk, cv, gv, bv, pq, pk, pv);

    dim3 gq3(CC / 128, (MR + 63) / 64, 3);
    mma_gemm_kernel<0><<<gq3, 256, GEMM_SMEM>>>(pq, rwq, qd, pk, rwk, kd, pv, rwv, vd,
                                                qs, nullptr, MR);

    dim3 fg((LSEQ + 63) / 64, BATCH * NHEAD);
    flash_mma_kernel<<<fg, 128, flash_smem>>>(qs, qd, kd, vd, ao);

    dim3 gp(CC / 128, (MR + 63) / 64, 1);
    mma_gemm_kernel<1><<<gp, 256, GEMM_SMEM>>>(ao, rwp, out, nullptr, nullptr, nullptr,
                                               nullptr, nullptr, nullptr, nullptr, bp, MR);
}